// round 2
// baseline (speedup 1.0000x reference)
#include <cuda_runtime.h>
#include <math.h>
#include <stdint.h>

#define Bn   128
#define Dd   512
#define Tt   33
#define Ll   32
#define Vv   10000
#define G4   2048

// ---------------- static device scratch ------------------------------------
__device__ float g_X  [Tt * Bn * Dd];        // per-step inputs        8.6 MB
__device__ float g_Gx [2 * Tt * Bn * G4];    // x-side gates           69 MB
__device__ float g_H  [Ll * Bn * Dd];        // normalized h history
__device__ float g_h  [Bn * Dd];             // carried h (normalized)
__device__ float g_hm [Bn * Dd];             // h after layer 0
__device__ float g_hr [Bn * Dd];             // h after layer 1 (pre-LN)
__device__ float g_c  [Bn * Dd];             // carried c
__device__ int   g_cap64;

// ---------------- utility kernels -------------------------------------------
__global__ void k_init() {
    int i = blockIdx.x * blockDim.x + threadIdx.x;
    if (i < Bn * Dd) { g_h[i] = 0.f; g_c[i] = 0.f; }
}

// caption int64 vs int32 detection (values < 10000 => int64 high words all 0)
__global__ void k_detect(const int* __restrict__ cap) {
    int any = 0;
    for (int i = threadIdx.x; i < 2048; i += blockDim.x)
        if (cap[2 * i + 1] != 0) any = 1;
    any = __syncthreads_or(any);
    if (threadIdx.x == 0) g_cap64 = any ? 0 : 1;
}

__global__ void k_build_x(const float* __restrict__ features,
                          const void*  __restrict__ cap,
                          const float* __restrict__ embW) {
    int blk = blockIdx.x;
    int t = blk >> 7;
    int b = blk & 127;
    const float* src;
    if (t == 0) {
        src = features + (size_t)b * Dd;
    } else {
        long long idx;
        if (g_cap64) idx = ((const long long*)cap)[b * Ll + (t - 1)];
        else         idx = (long long)((const int*)cap)[b * Ll + (t - 1)];
        src = embW + (size_t)idx * Dd;
    }
    float4*       dst = (float4*)(g_X + ((size_t)t * Bn + b) * Dd);
    const float4* s4  = (const float4*)src;
    dst[threadIdx.x] = s4[threadIdx.x];     // 128 threads x float4 = 512 floats
}

// ---------------- tf32 helpers ----------------------------------------------
__device__ __forceinline__ unsigned f2t(float x) {
    unsigned r;
    asm("cvt.rna.tf32.f32 %0, %1;" : "=r"(r) : "f"(x));
    return r;
}

__device__ __forceinline__ void mma_tf32(float* c, const unsigned* a, const unsigned* b) {
    asm volatile(
        "mma.sync.aligned.m16n8k8.row.col.f32.tf32.tf32.f32 "
        "{%0,%1,%2,%3}, {%4,%5,%6,%7}, {%8,%9}, {%0,%1,%2,%3};\n"
        : "+f"(c[0]), "+f"(c[1]), "+f"(c[2]), "+f"(c[3])
        : "r"(a[0]), "r"(a[1]), "r"(a[2]), "r"(a[3]), "r"(b[0]), "r"(b[1]));
}

// ---------------- generic GEMM: C = A(MxK) * B(NxK)^T ------------------------
// EPI 0: C[m][n] = acc + bias1[n] + bias2[n]               (Gx precompute)
// EPI 1: FC store with row permutation (m = (t-1)*128+b  ->  out row b*32+(t-1))
// EPI 2: fused LSTM cell (B rows gathered gate-interleaved, N assumed 2048)
// PREC 1: single tf32. PREC 3: tf32x3 split precision (fp32-accurate).
template<int BM, int BN, int WM, int WN, int EPI, int PREC>
__global__ void __launch_bounds__(WM * WN * 32)
gemm_tf32(const float* __restrict__ A, int M, int lda,
          const float* __restrict__ Bm, int N, int ldb, int K,
          const float* __restrict__ bias1, const float* __restrict__ bias2,
          float* __restrict__ C, int ldc,
          const float* __restrict__ gx, float* __restrict__ cst,
          float* __restrict__ hout)
{
    constexpr int THREADS = WM * WN * 32;
    constexpr int PAD = 4;
    constexpr int MF = 2, NF = 4;              // warp tile 32x32

    __shared__ unsigned Ash[16][BM + PAD];
    __shared__ unsigned Bsh[16][BN + PAD];
    __shared__ unsigned Asl[(PREC == 3) ? 16 : 1][BM + PAD];
    __shared__ unsigned Bsl[(PREC == 3) ? 16 : 1][BN + PAD];
    __shared__ float    Cs[(EPI == 2) ? BM * (BN + PAD) : 1];

    const int tid  = threadIdx.x;
    const int lane = tid & 31;
    const int warp = tid >> 5;
    const int wn = warp % WN, wm = warp / WN;
    const int gid = lane >> 2, t4 = lane & 3;
    const int m0 = blockIdx.x * BM;
    const int n0 = blockIdx.y * BN;
    const int jbase = blockIdx.y * (BN / 4);   // EPI 2 only

    float acc[MF][NF][4];
#pragma unroll
    for (int i = 0; i < MF; i++)
#pragma unroll
        for (int j = 0; j < NF; j++)
#pragma unroll
            for (int q = 0; q < 4; q++) acc[i][j][q] = 0.f;

    constexpr int LA = (BM * 16) / (THREADS * 4);
    constexpr int LB = (BN * 16) / (THREADS * 4);

#define SPLIT_STORE(AH, AL, KK, IDX, VAL)                               \
    { unsigned h_ = f2t(VAL); AH[KK][IDX] = h_;                         \
      if (PREC == 3) AL[KK][IDX] = f2t((VAL) - __uint_as_float(h_)); }

    for (int k0 = 0; k0 < K; k0 += 16) {
#pragma unroll
        for (int i = 0; i < LA; i++) {
            int f4 = tid + i * THREADS;
            int row = f4 >> 2, cb = f4 & 3;
            float4 v = make_float4(0.f, 0.f, 0.f, 0.f);
            int gm = m0 + row;
            if (gm < M) v = *(const float4*)(A + (size_t)gm * lda + k0 + cb * 4);
            SPLIT_STORE(Ash, Asl, cb * 4 + 0, row, v.x);
            SPLIT_STORE(Ash, Asl, cb * 4 + 1, row, v.y);
            SPLIT_STORE(Ash, Asl, cb * 4 + 2, row, v.z);
            SPLIT_STORE(Ash, Asl, cb * 4 + 3, row, v.w);
        }
#pragma unroll
        for (int i = 0; i < LB; i++) {
            int f4 = tid + i * THREADS;
            int row = f4 >> 2, cb = f4 & 3;
            int grow;
            if (EPI == 2) grow = ((row & 3) << 9) + jbase + (row >> 2); // gate interleave
            else          grow = n0 + row;
            float4 v = make_float4(0.f, 0.f, 0.f, 0.f);
            if (EPI == 2 || grow < N)
                v = *(const float4*)(Bm + (size_t)grow * ldb + k0 + cb * 4);
            SPLIT_STORE(Bsh, Bsl, cb * 4 + 0, row, v.x);
            SPLIT_STORE(Bsh, Bsl, cb * 4 + 1, row, v.y);
            SPLIT_STORE(Bsh, Bsl, cb * 4 + 2, row, v.z);
            SPLIT_STORE(Bsh, Bsl, cb * 4 + 3, row, v.w);
        }
        __syncthreads();

#pragma unroll
        for (int ks = 0; ks < 2; ks++) {
            const int kb = ks * 8;
            unsigned ah[MF][4], al[MF][4], bh[NF][2], bl[NF][2];
#pragma unroll
            for (int mf = 0; mf < MF; mf++) {
                int mm = wm * 32 + mf * 16 + gid;
                ah[mf][0] = Ash[kb + t4    ][mm];
                ah[mf][1] = Ash[kb + t4    ][mm + 8];
                ah[mf][2] = Ash[kb + t4 + 4][mm];
                ah[mf][3] = Ash[kb + t4 + 4][mm + 8];
                if (PREC == 3) {
                    al[mf][0] = Asl[kb + t4    ][mm];
                    al[mf][1] = Asl[kb + t4    ][mm + 8];
                    al[mf][2] = Asl[kb + t4 + 4][mm];
                    al[mf][3] = Asl[kb + t4 + 4][mm + 8];
                }
            }
#pragma unroll
            for (int nf = 0; nf < NF; nf++) {
                int nn = wn * 32 + nf * 8 + gid;
                bh[nf][0] = Bsh[kb + t4    ][nn];
                bh[nf][1] = Bsh[kb + t4 + 4][nn];
                if (PREC == 3) {
                    bl[nf][0] = Bsl[kb + t4    ][nn];
                    bl[nf][1] = Bsl[kb + t4 + 4][nn];
                }
            }
#pragma unroll
            for (int mf = 0; mf < MF; mf++)
#pragma unroll
                for (int nf = 0; nf < NF; nf++) {
                    mma_tf32(acc[mf][nf], ah[mf], bh[nf]);
                    if (PREC == 3) {
                        mma_tf32(acc[mf][nf], al[mf], bh[nf]);
                        mma_tf32(acc[mf][nf], ah[mf], bl[nf]);
                    }
                }
        }
        __syncthreads();
    }

    if (EPI == 0 || EPI == 1) {
#pragma unroll
        for (int mf = 0; mf < MF; mf++)
#pragma unroll
            for (int nf = 0; nf < NF; nf++) {
                int r0 = m0 + wm * 32 + mf * 16 + gid;
                int c0 = n0 + wn * 32 + nf * 8 + 2 * t4;
#pragma unroll
                for (int q = 0; q < 4; q++) {
                    int r = r0 + ((q >= 2) ? 8 : 0);
                    int c = c0 + (q & 1);
                    if (r < M && c < N) {
                        float v = acc[mf][nf][q];
                        if (bias1) v += bias1[c];
                        if (bias2) v += bias2[c];
                        if (EPI == 0) {
                            C[(size_t)r * ldc + c] = v;
                        } else {
                            int orow = (r & 127) * Ll + (r >> 7);
                            C[(size_t)orow * ldc + c] = v;
                        }
                    }
                }
            }
    } else {
        // dump block-local gate-interleaved tile to smem
#pragma unroll
        for (int mf = 0; mf < MF; mf++)
#pragma unroll
            for (int nf = 0; nf < NF; nf++) {
                int r0 = wm * 32 + mf * 16 + gid;
                int c0 = wn * 32 + nf * 8 + 2 * t4;
                Cs[r0 * (BN + PAD) + c0    ] = acc[mf][nf][0];
                Cs[r0 * (BN + PAD) + c0 + 1] = acc[mf][nf][1];
                Cs[(r0 + 8) * (BN + PAD) + c0    ] = acc[mf][nf][2];
                Cs[(r0 + 8) * (BN + PAD) + c0 + 1] = acc[mf][nf][3];
            }
        __syncthreads();
        // LSTM cell: tile col p = jj*4 + gate, gate column j = jbase + jj
#pragma unroll
        for (int it = 0; it < (BM * (BN / 4)) / THREADS; it++) {
            int x    = tid + it * THREADS;
            int jj   = x & (BN / 4 - 1);
            int brow = x / (BN / 4);
            int b    = m0 + brow;
            int j    = jbase + jj;
            float gi = Cs[brow * (BN + PAD) + jj * 4 + 0] + gx[b * G4 + j];
            float gf = Cs[brow * (BN + PAD) + jj * 4 + 1] + gx[b * G4 + 512 + j];
            float gg = Cs[brow * (BN + PAD) + jj * 4 + 2] + gx[b * G4 + 1024 + j];
            float go = Cs[brow * (BN + PAD) + jj * 4 + 3] + gx[b * G4 + 1536 + j];
            float ii = 1.f / (1.f + expf(-gi));
            float ff = 1.f / (1.f + expf(-gf));
            float gt = tanhf(gg);
            float oo = 1.f / (1.f + expf(-go));
            float cn = ff * cst[b * Dd + j] + ii * gt;
            cst[b * Dd + j]  = cn;
            hout[b * Dd + j] = oo * tanhf(cn);
        }
    }
#undef SPLIT_STORE
}

// ---------------- layernorm + carry + history -------------------------------
__global__ void k_ln(const float* __restrict__ hraw,
                     const float* __restrict__ lng,
                     const float* __restrict__ lnb, int t) {
    __shared__ float sm[4];
    int b = blockIdx.x;
    int tid = threadIdx.x;            // 128 threads
    const float* x = hraw + (size_t)b * Dd;

    float s = 0.f;
    for (int i = tid; i < Dd; i += 128) s += x[i];
#pragma unroll
    for (int o = 16; o > 0; o >>= 1) s += __shfl_xor_sync(0xffffffffu, s, o);
    if ((tid & 31) == 0) sm[tid >> 5] = s;
    __syncthreads();
    float mu = (sm[0] + sm[1] + sm[2] + sm[3]) * (1.f / 512.f);
    __syncthreads();

    float v = 0.f;
    for (int i = tid; i < Dd; i += 128) { float d = x[i] - mu; v += d * d; }
#pragma unroll
    for (int o = 16; o > 0; o >>= 1) v += __shfl_xor_sync(0xffffffffu, v, o);
    if ((tid & 31) == 0) sm[tid >> 5] = v;
    __syncthreads();
    float var  = (sm[0] + sm[1] + sm[2] + sm[3]) * (1.f / 512.f);
    float rstd = rsqrtf(var + 1e-5f);

    for (int i = tid; i < Dd; i += 128) {
        float y = (x[i] - mu) * rstd * lng[i] + lnb[i];
        g_h[(size_t)b * Dd + i] = y;
        if (t > 0) g_H[((size_t)(t - 1) * Bn + b) * Dd + i] = y;
    }
}

// ---------------- in-place log_softmax, rows of 10000 ------------------------
__global__ void k_lsm(float* __restrict__ out) {
    __shared__ float row[Vv];
    __shared__ float red[8];
    float* p = out + (size_t)blockIdx.x * Vv;
    int tid = threadIdx.x;            // 256 threads

    float mx = -1e30f;
    float4*       r4 = (float4*)row;
    const float4* p4 = (const float4*)p;
    for (int i = tid; i < Vv / 4; i += 256) {
        float4 v = p4[i];
        r4[i] = v;
        mx = fmaxf(mx, fmaxf(fmaxf(v.x, v.y), fmaxf(v.z, v.w)));
    }
#pragma unroll
    for (int o = 16; o > 0; o >>= 1) mx = fmaxf(mx, __shfl_xor_sync(0xffffffffu, mx, o));
    if ((tid & 31) == 0) red[tid >> 5] = mx;
    __syncthreads();
    mx = red[0];
#pragma unroll
    for (int i = 1; i < 8; i++) mx = fmaxf(mx, red[i]);

    float s = 0.f;
    for (int i = tid; i < Vv; i += 256) s += expf(row[i] - mx);
#pragma unroll
    for (int o = 16; o > 0; o >>= 1) s += __shfl_xor_sync(0xffffffffu, s, o);
    __syncthreads();
    if ((tid & 31) == 0) red[tid >> 5] = s;
    __syncthreads();
    s = red[0] + red[1] + red[2] + red[3] + red[4] + red[5] + red[6] + red[7];
    float lse = mx + logf(s);

    for (int i = tid; i < Vv; i += 256) p[i] = row[i] - lse;
}

// ---------------- host launcher ----------------------------------------------
extern "C" void kernel_launch(void* const* d_in, const int* in_sizes, int n_in,
                              void* d_out, int out_size) {
    const float* features = (const float*)d_in[0];
    const void*  caption  = d_in[1];
    const float* embW     = (const float*)d_in[2];
    const float* Wih      = (const float*)d_in[3];
    const float* Whh      = (const float*)d_in[4];
    const float* bih      = (const float*)d_in[5];
    const float* bhh      = (const float*)d_in[6];
    const float* lng      = (const float*)d_in[7];
    const float* lnb      = (const float*)d_in[8];
    const float* fcW      = (const float*)d_in[9];
    const float* fcb      = (const float*)d_in[10];
    float*       out      = (float*)d_out;

    float *pX, *pGx, *pH, *ph, *phm, *phr, *pc;
    cudaGetSymbolAddress((void**)&pX,  g_X);
    cudaGetSymbolAddress((void**)&pGx, g_Gx);
    cudaGetSymbolAddress((void**)&pH,  g_H);
    cudaGetSymbolAddress((void**)&ph,  g_h);
    cudaGetSymbolAddress((void**)&phm, g_hm);
    cudaGetSymbolAddress((void**)&phr, g_hr);
    cudaGetSymbolAddress((void**)&pc,  g_c);

    k_init<<<256, 256>>>();
    k_detect<<<1, 256>>>((const int*)caption);
    k_build_x<<<Tt * Bn, 128>>>(features, caption, embW);

    // Gx = X @ Wih^T + bih + bhh   (both layers, tf32x3)
    for (int l = 0; l < 2; l++)
        gemm_tf32<128, 64, 4, 2, 0, 3><<<dim3(33, 32), 256>>>(
            pX, Tt * Bn, Dd,
            Wih + (size_t)l * G4 * Dd, G4, Dd, Dd,
            bih + l * G4, bhh + l * G4,
            pGx + (size_t)l * Tt * Bn * G4, G4,
            nullptr, nullptr, nullptr);

    for (int t = 0; t < Tt; t++) {
        gemm_tf32<64, 64, 2, 2, 2, 3><<<dim3(2, 32), 128>>>(
            ph, Bn, Dd, Whh, G4, Dd, Dd,
            nullptr, nullptr, nullptr, 0,
            pGx + (size_t)t * Bn * G4, pc, phm);
        gemm_tf32<64, 64, 2, 2, 2, 3><<<dim3(2, 32), 128>>>(
            phm, Bn, Dd, Whh + (size_t)G4 * Dd, G4, Dd, Dd,
            nullptr, nullptr, nullptr, 0,
            pGx + ((size_t)Tt + t) * Bn * G4, pc, phr);
        k_ln<<<128, 128>>>(phr, lng, lnb, t);
    }

    // FC: logits = H @ fcW^T + fcb  (single tf32, permuted store)
    gemm_tf32<128, 64, 4, 2, 1, 1><<<dim3(32, 157), 256>>>(
        pH, Ll * Bn, Dd, fcW, Vv, Dd, Dd,
        fcb, nullptr, out, Vv,
        nullptr, nullptr, nullptr);

    k_lsm<<<Ll * Bn, 256>>>(out);
}

// round 4
// speedup vs baseline: 1.2524x; 1.2524x over previous
#include <cuda_runtime.h>
#include <math.h>
#include <stdint.h>

#define Bn   128
#define Dd   512
#define Tt   33
#define Ll   32
#define Vv   10000
#define G4   2048

// ---------------- static device scratch ------------------------------------
__device__ float    g_X  [Tt * Bn * Dd];        // per-step inputs
__device__ float    g_Gx [2 * Tt * Bn * G4];    // x-side gates (both layers)
__device__ float    g_H  [Ll * Bn * Dd];        // normalized h history
__device__ float    g_h  [Bn * Dd];             // carried h (normalized)
__device__ float    g_hm [Bn * Dd];             // h after layer 0
__device__ float    g_hr [Bn * Dd];             // h after layer 1 (pre-LN)
__device__ unsigned g_Bhi[2 * G4 * Dd];         // Whh gate-interleaved tf32 hi
__device__ unsigned g_Blo[2 * G4 * Dd];         // Whh gate-interleaved tf32 lo
__device__ unsigned g_bar;                      // grid barrier counter
__device__ int      g_cap64;

// ---------------- utility kernels -------------------------------------------
__global__ void k_init() {
    int i = blockIdx.x * blockDim.x + threadIdx.x;
    if (i < Bn * Dd) g_h[i] = 0.f;
    if (i == 0) g_bar = 0u;
}

// caption int64 vs int32 detection (values < 10000 => int64 high words all 0)
__global__ void k_detect(const int* __restrict__ cap) {
    int any = 0;
    for (int i = threadIdx.x; i < 2048; i += blockDim.x)
        if (cap[2 * i + 1] != 0) any = 1;
    any = __syncthreads_or(any);
    if (threadIdx.x == 0) g_cap64 = any ? 0 : 1;
}

__global__ void k_build_x(const float* __restrict__ features,
                          const void*  __restrict__ cap,
                          const float* __restrict__ embW) {
    int blk = blockIdx.x;
    int t = blk >> 7;
    int b = blk & 127;
    const float* src;
    if (t == 0) {
        src = features + (size_t)b * Dd;
    } else {
        long long idx;
        if (g_cap64) idx = ((const long long*)cap)[b * Ll + (t - 1)];
        else         idx = (long long)((const int*)cap)[b * Ll + (t - 1)];
        src = embW + (size_t)idx * Dd;
    }
    float4*       dst = (float4*)(g_X + ((size_t)t * Bn + b) * Dd);
    const float4* s4  = (const float4*)src;
    dst[threadIdx.x] = s4[threadIdx.x];
}

// ---------------- tf32 helpers ----------------------------------------------
__device__ __forceinline__ unsigned f2t(float x) {
    unsigned r;
    asm("cvt.rna.tf32.f32 %0, %1;" : "=r"(r) : "f"(x));
    return r;
}

__device__ __forceinline__ void mma_tf32(float* c, const unsigned* a, const unsigned* b) {
    asm volatile(
        "mma.sync.aligned.m16n8k8.row.col.f32.tf32.tf32.f32 "
        "{%0,%1,%2,%3}, {%4,%5,%6,%7}, {%8,%9}, {%0,%1,%2,%3};\n"
        : "+f"(c[0]), "+f"(c[1]), "+f"(c[2]), "+f"(c[3])
        : "r"(a[0]), "r"(a[1]), "r"(a[2]), "r"(a[3]), "r"(b[0]), "r"(b[1]));
}

// Pre-convert Whh to gate-interleaved tf32 hi/lo.
// Interleaved row p = 4*j + g  maps to original row (g<<9) + j.
__global__ void k_prep(const float* __restrict__ Whh) {
    int blk = blockIdx.x;            // 0..4095
    int l = blk >> 11, p = blk & 2047;
    int g = p & 3, j = p >> 2;
    const float* src = Whh + ((size_t)l * G4 + (g << 9) + j) * Dd;
    unsigned* dh = g_Bhi + ((size_t)l * G4 + p) * Dd;
    unsigned* dl = g_Blo + ((size_t)l * G4 + p) * Dd;
    for (int i = threadIdx.x; i < Dd; i += 128) {
        float v = src[i];
        unsigned h = f2t(v);
        dh[i] = h;
        dl[i] = f2t(v - __uint_as_float(h));
    }
}

// ---------------- grid barrier (persistent kernel, single wave) -------------
__device__ __forceinline__ void grid_barrier(unsigned& target) {
    __syncthreads();
    if (threadIdx.x == 0) {
        target += gridDim.x;
        __threadfence();
        atomicAdd(&g_bar, 1u);
        while (*((volatile unsigned*)&g_bar) < target) { }
        __threadfence();
    }
    __syncthreads();
}

// ---------------- persistent recurrence kernel -------------------------------
// 128 CTAs x 128 threads = 4 batch-groups (32 rows) x 32 j-groups (16 cols).
// Per step: layer0 GEMM+cell | bar | layer1 GEMM+cell | bar | LN (1 row/CTA) | bar
__global__ void __launch_bounds__(128, 1)
k_recurrence(const float* __restrict__ lng, const float* __restrict__ lnb) {
    // staging: Ah(16x36) Al(16x36) Bh(16x68) Bl(16x68) = 13312 B, unioned with
    // Cs (32x68 floats = 8704 B)
    __shared__ __align__(16) char sbuf[13312];
    unsigned (*Ah)[36] = (unsigned(*)[36])(sbuf);
    unsigned (*Al)[36] = (unsigned(*)[36])(sbuf + 2304);
    unsigned (*Bh)[68] = (unsigned(*)[68])(sbuf + 4608);
    unsigned (*Bl)[68] = (unsigned(*)[68])(sbuf + 8960);
    float    (*Cs)[68] = (float(*)[68])   (sbuf);
    __shared__ float csm[32][16];      // cell-state slice, resident all steps
    __shared__ float red[4];

    const int tid  = threadIdx.x;
    const int lane = tid & 31;
    const int warp = tid >> 5;
    const int gid  = lane >> 2, t4 = lane & 3;
    const int cta  = blockIdx.x;            // 0..127
    const int jcta = cta & 31;              // j-group
    const int bm0  = (cta >> 5) * 32;       // batch-group base row
    const int jbase = jcta * 16;
    const int wm = warp >> 1, wn = warp & 1; // 2x2 warps over 32x64 tile
    unsigned target = 0;

    for (int i = tid; i < 32 * 16; i += 128) csm[i >> 4][i & 15] = 0.f;
    __syncthreads();

    for (int t = 0; t < Tt; t++) {
#pragma unroll 1
        for (int l = 0; l < 2; l++) {
            const float*    A    = (l == 0) ? g_h : g_hm;
            const unsigned* Bhg  = g_Bhi + ((size_t)l * G4 + jcta * 64) * Dd;
            const unsigned* Blg  = g_Blo + ((size_t)l * G4 + jcta * 64) * Dd;
            const float*    gx   = g_Gx + ((size_t)l * Tt + t) * Bn * G4;
            float*          hout = (l == 0) ? g_hm : g_hr;

            float acc[4][4];       // nf x quad  (warp tile 16x32)
#pragma unroll
            for (int b = 0; b < 4; b++)
#pragma unroll
                for (int q = 0; q < 4; q++) acc[b][q] = 0.f;

            for (int k0 = 0; k0 < Dd; k0 += 16) {
                // A tile [32 x 16] hi/lo: 128 threads x 1 float4
                {
                    int row = tid >> 2, cb = tid & 3;
                    float4 v = *(const float4*)(A + (size_t)(bm0 + row) * Dd + k0 + cb * 4);
                    unsigned h0 = f2t(v.x), h1 = f2t(v.y), h2 = f2t(v.z), h3 = f2t(v.w);
                    Ah[cb * 4 + 0][row] = h0; Al[cb * 4 + 0][row] = f2t(v.x - __uint_as_float(h0));
                    Ah[cb * 4 + 1][row] = h1; Al[cb * 4 + 1][row] = f2t(v.y - __uint_as_float(h1));
                    Ah[cb * 4 + 2][row] = h2; Al[cb * 4 + 2][row] = f2t(v.z - __uint_as_float(h2));
                    Ah[cb * 4 + 3][row] = h3; Al[cb * 4 + 3][row] = f2t(v.w - __uint_as_float(h3));
                }
                // B tile [64 x 16] pre-converted: 128 threads x 2 uint4 (hi+lo)
#pragma unroll
                for (int i = 0; i < 2; i++) {
                    int f  = tid + i * 128;
                    int pp = f >> 2, q4 = f & 3;
                    uint4 vh = *(const uint4*)(Bhg + (size_t)pp * Dd + k0 + q4 * 4);
                    uint4 vl = *(const uint4*)(Blg + (size_t)pp * Dd + k0 + q4 * 4);
                    Bh[q4 * 4 + 0][pp] = vh.x; Bh[q4 * 4 + 1][pp] = vh.y;
                    Bh[q4 * 4 + 2][pp] = vh.z; Bh[q4 * 4 + 3][pp] = vh.w;
                    Bl[q4 * 4 + 0][pp] = vl.x; Bl[q4 * 4 + 1][pp] = vl.y;
                    Bl[q4 * 4 + 2][pp] = vl.z; Bl[q4 * 4 + 3][pp] = vl.w;
                }
                __syncthreads();
#pragma unroll
                for (int ks = 0; ks < 2; ks++) {
                    const int kb = ks * 8;
                    unsigned ah[4], al[4], bh[4][2], bl[4][2];
                    int mm = wm * 16 + gid;
                    ah[0] = Ah[kb + t4    ][mm];
                    ah[1] = Ah[kb + t4    ][mm + 8];
                    ah[2] = Ah[kb + t4 + 4][mm];
                    ah[3] = Ah[kb + t4 + 4][mm + 8];
                    al[0] = Al[kb + t4    ][mm];
                    al[1] = Al[kb + t4    ][mm + 8];
                    al[2] = Al[kb + t4 + 4][mm];
                    al[3] = Al[kb + t4 + 4][mm + 8];
#pragma unroll
                    for (int nf = 0; nf < 4; nf++) {
                        int nn = wn * 32 + nf * 8 + gid;
                        bh[nf][0] = Bh[kb + t4    ][nn];
                        bh[nf][1] = Bh[kb + t4 + 4][nn];
                        bl[nf][0] = Bl[kb + t4    ][nn];
                        bl[nf][1] = Bl[kb + t4 + 4][nn];
                    }
#pragma unroll
                    for (int nf = 0; nf < 4; nf++) {
                        mma_tf32(acc[nf], ah, bh[nf]);
                        mma_tf32(acc[nf], al, bh[nf]);
                        mma_tf32(acc[nf], ah, bl[nf]);
                    }
                }
                __syncthreads();
            }
            // accumulators -> Cs (aliases staging; safe after last sync)
#pragma unroll
            for (int nf = 0; nf < 4; nf++) {
                int r0 = wm * 16 + gid;
                int c0 = wn * 32 + nf * 8 + 2 * t4;
                Cs[r0    ][c0    ] = acc[nf][0];
                Cs[r0    ][c0 + 1] = acc[nf][1];
                Cs[r0 + 8][c0    ] = acc[nf][2];
                Cs[r0 + 8][c0 + 1] = acc[nf][3];
            }
            __syncthreads();
            // LSTM cell: 32x16 = 512 elements, 4 per thread
#pragma unroll
            for (int it = 0; it < 4; it++) {
                int x    = tid + it * 128;
                int brow = x >> 4, jj = x & 15;
                int b    = bm0 + brow;
                int j    = jbase + jj;
                float gi = Cs[brow][jj * 4 + 0] + gx[b * G4 + j];
                float gf = Cs[brow][jj * 4 + 1] + gx[b * G4 + 512 + j];
                float gg = Cs[brow][jj * 4 + 2] + gx[b * G4 + 1024 + j];
                float go = Cs[brow][jj * 4 + 3] + gx[b * G4 + 1536 + j];
                float ii = 1.f / (1.f + expf(-gi));
                float ff = 1.f / (1.f + expf(-gf));
                float gt = tanhf(gg);
                float oo = 1.f / (1.f + expf(-go));
                float cn = ff * csm[brow][jj] + ii * gt;
                csm[brow][jj] = cn;
                hout[(size_t)b * Dd + j] = oo * tanhf(cn);
            }
            grid_barrier(target);
        }
        // ---- LayerNorm: CTA handles batch row b = cta ----
        {
            const float* xr = g_hr + (size_t)cta * Dd;
            float v0[4];
            float s = 0.f;
#pragma unroll
            for (int i = 0; i < 4; i++) { v0[i] = xr[tid + i * 128]; s += v0[i]; }
#pragma unroll
            for (int o = 16; o > 0; o >>= 1) s += __shfl_xor_sync(0xffffffffu, s, o);
            if (lane == 0) red[warp] = s;
            __syncthreads();
            float mu = (red[0] + red[1] + red[2] + red[3]) * (1.f / 512.f);
            __syncthreads();
            float vv = 0.f;
#pragma unroll
            for (int i = 0; i < 4; i++) { float d = v0[i] - mu; vv += d * d; }
#pragma unroll
            for (int o = 16; o > 0; o >>= 1) vv += __shfl_xor_sync(0xffffffffu, vv, o);
            if (lane == 0) red[warp] = vv;
            __syncthreads();
            float var  = (red[0] + red[1] + red[2] + red[3]) * (1.f / 512.f);
            float rstd = rsqrtf(var + 1e-5f);
#pragma unroll
            for (int i = 0; i < 4; i++) {
                int idx = tid + i * 128;
                float y = (v0[i] - mu) * rstd * lng[idx] + lnb[idx];
                g_h[(size_t)cta * Dd + idx] = y;
                if (t > 0) g_H[((size_t)(t - 1) * Bn + cta) * Dd + idx] = y;
            }
            __syncthreads();
        }
        grid_barrier(target);
    }
}

// ---------------- generic GEMM: C = A(MxK) * B(NxK)^T ------------------------
// EPI 0: C[m][n] = acc + bias1[n] + bias2[n]               (Gx precompute)
// EPI 1: FC store with row permutation (m = (t-1)*128+b -> out row b*32+(t-1))
// PREC 1: single tf32. PREC 3: tf32x3 split precision.
template<int BM, int BN, int WM, int WN, int EPI, int PREC>
__global__ void __launch_bounds__(WM * WN * 32)
gemm_tf32(const float* __restrict__ A, int M, int lda,
          const float* __restrict__ Bm, int N, int ldb, int K,
          const float* __restrict__ bias1, const float* __restrict__ bias2,
          float* __restrict__ C, int ldc)
{
    constexpr int THREADS = WM * WN * 32;
    constexpr int PAD = 4;
    constexpr int MF = 2, NF = 4;              // warp tile 32x32

    __shared__ unsigned Ash[16][BM + PAD];
    __shared__ unsigned Bsh[16][BN + PAD];
    __shared__ unsigned Asl[(PREC == 3) ? 16 : 1][BM + PAD];
    __shared__ unsigned Bsl[(PREC == 3) ? 16 : 1][BN + PAD];

    const int tid  = threadIdx.x;
    const int lane = tid & 31;
    const int warp = tid >> 5;
    const int wn = warp % WN, wm = warp / WN;
    const int gid = lane >> 2, t4 = lane & 3;
    const int m0 = blockIdx.x * BM;
    const int n0 = blockIdx.y * BN;

    float acc[MF][NF][4];
#pragma unroll
    for (int i = 0; i < MF; i++)
#pragma unroll
        for (int j = 0; j < NF; j++)
#pragma unroll
            for (int q = 0; q < 4; q++) acc[i][j][q] = 0.f;

    constexpr int LA = (BM * 16) / (THREADS * 4);
    constexpr int LB = (BN * 16) / (THREADS * 4);

#define SPLIT_STORE(AH, AL, KK, IDX, VAL)                               \
    { unsigned h_ = f2t(VAL); AH[KK][IDX] = h_;                         \
      if (PREC == 3) AL[KK][IDX] = f2t((VAL) - __uint_as_float(h_)); }

    for (int k0 = 0; k0 < K; k0 += 16) {
#pragma unroll
        for (int i = 0; i < LA; i++) {
            int f4 = tid + i * THREADS;
            int row = f4 >> 2, cb = f4 & 3;
            float4 v = make_float4(0.f, 0.f, 0.f, 0.f);
            int gm = m0 + row;
            if (gm < M) v = *(const float4*)(A + (size_t)gm * lda + k0 + cb * 4);
            SPLIT_STORE(Ash, Asl, cb * 4 + 0, row, v.x);
            SPLIT_STORE(Ash, Asl, cb * 4 + 1, row, v.y);
            SPLIT_STORE(Ash, Asl, cb * 4 + 2, row, v.z);
            SPLIT_STORE(Ash, Asl, cb * 4 + 3, row, v.w);
        }
#pragma unroll
        for (int i = 0; i < LB; i++) {
            int f4 = tid + i * THREADS;
            int row = f4 >> 2, cb = f4 & 3;
            int grow = n0 + row;
            float4 v = make_float4(0.f, 0.f, 0.f, 0.f);
            if (grow < N)
                v = *(const float4*)(Bm + (size_t)grow * ldb + k0 + cb * 4);
            SPLIT_STORE(Bsh, Bsl, cb * 4 + 0, row, v.x);
            SPLIT_STORE(Bsh, Bsl, cb * 4 + 1, row, v.y);
            SPLIT_STORE(Bsh, Bsl, cb * 4 + 2, row, v.z);
            SPLIT_STORE(Bsh, Bsl, cb * 4 + 3, row, v.w);
        }
        __syncthreads();

#pragma unroll
        for (int ks = 0; ks < 2; ks++) {
            const int kb = ks * 8;
            unsigned ah[MF][4], al[MF][4], bh[NF][2], bl[NF][2];
#pragma unroll
            for (int mf = 0; mf < MF; mf++) {
                int mm = wm * 32 + mf * 16 + gid;
                ah[mf][0] = Ash[kb + t4    ][mm];
                ah[mf][1] = Ash[kb + t4    ][mm + 8];
                ah[mf][2] = Ash[kb + t4 + 4][mm];
                ah[mf][3] = Ash[kb + t4 + 4][mm + 8];
                if (PREC == 3) {
                    al[mf][0] = Asl[kb + t4    ][mm];
                    al[mf][1] = Asl[kb + t4    ][mm + 8];
                    al[mf][2] = Asl[kb + t4 + 4][mm];
                    al[mf][3] = Asl[kb + t4 + 4][mm + 8];
                }
            }
#pragma unroll
            for (int nf = 0; nf < NF; nf++) {
                int nn = wn * 32 + nf * 8 + gid;
                bh[nf][0] = Bsh[kb + t4    ][nn];
                bh[nf][1] = Bsh[kb + t4 + 4][nn];
                if (PREC == 3) {
                    bl[nf][0] = Bsl[kb + t4    ][nn];
                    bl[nf][1] = Bsl[kb + t4 + 4][nn];
                }
            }
#pragma unroll
            for (int mf = 0; mf < MF; mf++)
#pragma unroll
                for (int nf = 0; nf < NF; nf++) {
                    mma_tf32(acc[mf][nf], ah[mf], bh[nf]);
                    if (PREC == 3) {
                        mma_tf32(acc[mf][nf], al[mf], bh[nf]);
                        mma_tf32(acc[mf][nf], ah[mf], bl[nf]);
                    }
                }
        }
        __syncthreads();
    }

#pragma unroll
    for (int mf = 0; mf < MF; mf++)
#pragma unroll
        for (int nf = 0; nf < NF; nf++) {
            int r0 = m0 + wm * 32 + mf * 16 + gid;
            int c0 = n0 + wn * 32 + nf * 8 + 2 * t4;
#pragma unroll
            for (int q = 0; q < 4; q++) {
                int r = r0 + ((q >= 2) ? 8 : 0);
                int c = c0 + (q & 1);
                if (r < M && c < N) {
                    float v = acc[mf][nf][q];
                    if (bias1) v += bias1[c];
                    if (bias2) v += bias2[c];
                    if (EPI == 0) {
                        C[(size_t)r * ldc + c] = v;
                    } else {
                        int orow = (r & 127) * Ll + (r >> 7);
                        C[(size_t)orow * ldc + c] = v;
                    }
                }
            }
        }
#undef SPLIT_STORE
}

// ---------------- in-place log_softmax, rows of 10000 ------------------------
__global__ void k_lsm(float* __restrict__ out) {
    __shared__ float row[Vv];
    __shared__ float red[8];
    float* p = out + (size_t)blockIdx.x * Vv;
    int tid = threadIdx.x;            // 256 threads

    float mx = -1e30f;
    float4*       r4 = (float4*)row;
    const float4* p4 = (const float4*)p;
    for (int i = tid; i < Vv / 4; i += 256) {
        float4 v = p4[i];
        r4[i] = v;
        mx = fmaxf(mx, fmaxf(fmaxf(v.x, v.y), fmaxf(v.z, v.w)));
    }
#pragma unroll
    for (int o = 16; o > 0; o >>= 1) mx = fmaxf(mx, __shfl_xor_sync(0xffffffffu, mx, o));
    if ((tid & 31) == 0) red[tid >> 5] = mx;
    __syncthreads();
    mx = red[0];
#pragma unroll
    for (int i = 1; i < 8; i++) mx = fmaxf(mx, red[i]);

    float s = 0.f;
    for (int i = tid; i < Vv; i += 256) s += expf(row[i] - mx);
#pragma unroll
    for (int o = 16; o > 0; o >>= 1) s += __shfl_xor_sync(0xffffffffu, s, o);
    __syncthreads();
    if ((tid & 31) == 0) red[tid >> 5] = s;
    __syncthreads();
    s = red[0] + red[1] + red[2] + red[3] + red[4] + red[5] + red[6] + red[7];
    float lse = mx + logf(s);

    for (int i = tid; i < Vv; i += 256) p[i] = row[i] - lse;
}

// ---------------- host launcher ----------------------------------------------
extern "C" void kernel_launch(void* const* d_in, const int* in_sizes, int n_in,
                              void* d_out, int out_size) {
    const float* features = (const float*)d_in[0];
    const void*  caption  = d_in[1];
    const float* embW     = (const float*)d_in[2];
    const float* Wih      = (const float*)d_in[3];
    const float* Whh      = (const float*)d_in[4];
    const float* bih      = (const float*)d_in[5];
    const float* bhh      = (const float*)d_in[6];
    const float* lng      = (const float*)d_in[7];
    const float* lnb      = (const float*)d_in[8];
    const float* fcW      = (const float*)d_in[9];
    const float* fcb      = (const float*)d_in[10];
    float*       out      = (float*)d_out;

    float *pX, *pGx, *pH;
    cudaGetSymbolAddress((void**)&pX,  g_X);
    cudaGetSymbolAddress((void**)&pGx, g_Gx);
    cudaGetSymbolAddress((void**)&pH,  g_H);

    k_init<<<256, 256>>>();
    k_detect<<<1, 256>>>((const int*)caption);
    k_build_x<<<Tt * Bn, 128>>>(features, caption, embW);
    k_prep<<<2 * G4, 128>>>(Whh);

    // Gx = X @ Wih^T + bih + bhh   (both layers, tf32x3)
    for (int l = 0; l < 2; l++)
        gemm_tf32<128, 64, 4, 2, 0, 3><<<dim3(33, 32), 256>>>(
            pX, Tt * Bn, Dd,
            Wih + (size_t)l * G4 * Dd, G4, Dd, Dd,
            bih + l * G4, bhh + l * G4,
            pGx + (size_t)l * Tt * Bn * G4, G4);

    // full 33-step recurrence in ONE persistent kernel (single wave)
    k_recurrence<<<128, 128>>>(lng, lnb);

    // FC: logits = H @ fcW^T + fcb  (single tf32, permuted store)
    gemm_tf32<128, 64, 4, 2, 1, 1><<<dim3(32, 157), 256>>>(
        pH, Ll * Bn, Dd, fcW, Vv, Dd, Dd,
        fcb, nullptr, out, Vv);

    k_lsm<<<Ll * Bn, 256>>>(out);
}

// round 5
// speedup vs baseline: 1.5553x; 1.2418x over previous
#include <cuda_runtime.h>
#include <math.h>
#include <stdint.h>

#define Bn   128
#define Dd   512
#define Tt   33
#define Ll   32
#define Vv   10000
#define G4   2048

// ---------------- static device scratch ------------------------------------
__device__ float    g_X  [Tt * Bn * Dd];        // per-step inputs
__device__ float    g_Gx [2 * Tt * Bn * G4];    // x-side gates (both layers)
__device__ float    g_H  [Ll * Bn * Dd];        // normalized h history
__device__ float    g_h  [Bn * Dd];             // carried h (normalized)
__device__ float    g_hm [Bn * Dd];             // h after layer 0
__device__ float    g_hr [Bn * Dd];             // h after layer 1 (pre-LN)
__device__ unsigned g_bar;                      // grid barrier counter
__device__ int      g_cap64;

// ---------------- utility kernels -------------------------------------------
__global__ void k_init() {
    int i = blockIdx.x * blockDim.x + threadIdx.x;
    if (i < Bn * Dd) g_h[i] = 0.f;
    if (i == 0) g_bar = 0u;
}

// caption int64 vs int32 detection (values < 10000 => int64 high words all 0)
__global__ void k_detect(const int* __restrict__ cap) {
    int any = 0;
    for (int i = threadIdx.x; i < 2048; i += blockDim.x)
        if (cap[2 * i + 1] != 0) any = 1;
    any = __syncthreads_or(any);
    if (threadIdx.x == 0) g_cap64 = any ? 0 : 1;
}

__global__ void k_build_x(const float* __restrict__ features,
                          const void*  __restrict__ cap,
                          const float* __restrict__ embW) {
    int blk = blockIdx.x;
    int t = blk >> 7;
    int b = blk & 127;
    const float* src;
    if (t == 0) {
        src = features + (size_t)b * Dd;
    } else {
        long long idx;
        if (g_cap64) idx = ((const long long*)cap)[b * Ll + (t - 1)];
        else         idx = (long long)((const int*)cap)[b * Ll + (t - 1)];
        src = embW + (size_t)idx * Dd;
    }
    float4*       dst = (float4*)(g_X + ((size_t)t * Bn + b) * Dd);
    const float4* s4  = (const float4*)src;
    dst[threadIdx.x] = s4[threadIdx.x];
}

// ---------------- tf32 helpers ----------------------------------------------
__device__ __forceinline__ unsigned f2t(float x) {
    unsigned r;
    asm("cvt.rna.tf32.f32 %0, %1;" : "=r"(r) : "f"(x));
    return r;
}

__device__ __forceinline__ void mma_tf32(float* c, const unsigned* a, const unsigned* b) {
    asm volatile(
        "mma.sync.aligned.m16n8k8.row.col.f32.tf32.tf32.f32 "
        "{%0,%1,%2,%3}, {%4,%5,%6,%7}, {%8,%9}, {%0,%1,%2,%3};\n"
        : "+f"(c[0]), "+f"(c[1]), "+f"(c[2]), "+f"(c[3])
        : "r"(a[0]), "r"(a[1]), "r"(a[2]), "r"(a[3]), "r"(b[0]), "r"(b[1]));
}

// ---------------- grid barrier (persistent kernel, single wave) -------------
__device__ __forceinline__ void grid_barrier(unsigned& target) {
    __syncthreads();
    if (threadIdx.x == 0) {
        target += gridDim.x;
        __threadfence();
        atomicAdd(&g_bar, 1u);
        while (*((volatile unsigned*)&g_bar) < target) { }
        __threadfence();
    }
    __syncthreads();
}

// ---------------- persistent recurrence kernel -------------------------------
// 128 CTAs x 256 threads = 2 batch-groups (64 rows) x 64 j-groups (8 cols).
// Whh slice for BOTH layers lives in shared memory for the whole kernel.
// smem layout (dynamic):
//   Bs   [2*32][516] fp32                      0      .. 132096
//   Ah   [2][16][68] u32 (dbl buf)             132096 .. 140800  } union with
//   Al   [2][16][68] u32 (dbl buf)             140800 .. 149504  } Cs[64][36]
//   csm  [64][8] fp32                          149504 .. 151552
//   red  [8] fp32                              151552 .. 151584
#define SMEM_REC 151616
__global__ void __launch_bounds__(256, 1)
k_recurrence(const float* __restrict__ Whh,
             const float* __restrict__ lng, const float* __restrict__ lnb) {
    extern __shared__ __align__(16) char sbuf[];
    float*    Bs       = (float*)sbuf;                          // [(l*32+row)*516 + k]
    unsigned (*Ah)[16][68] = (unsigned(*)[16][68])(sbuf + 132096);
    unsigned (*Al)[16][68] = (unsigned(*)[16][68])(sbuf + 140800);
    float    (*Cs)[36] = (float(*)[36])(sbuf + 132096);         // union w/ Ah/Al
    float    (*csm)[8] = (float(*)[8])(sbuf + 149504);
    float*    red      = (float*)(sbuf + 151552);

    const int tid  = threadIdx.x;
    const int lane = tid & 31;
    const int warp = tid >> 5;
    const int gid  = lane >> 2, t4 = lane & 3;
    const int cta  = blockIdx.x;             // 0..127
    const int jcta = cta & 63;               // j-group: cols [jcta*8, jcta*8+8)
    const int bm0  = (cta >> 6) * 64;        // batch-group base row
    const int wm   = warp >> 1, wn = warp & 1;  // 4x2 warps, warp tile 16x16
    unsigned target = 0;

    // ---- one-time: load this CTA's Whh slice (both layers), gate-interleaved
    // interleaved row p = jcta*32 + rl  <->  original row ((p&3)<<9) | (p>>2)
    for (int idx = tid; idx < 2 * 32 * 128; idx += 256) {
        int l  = idx >> 12;
        int rm = idx & 4095;
        int rl = rm >> 7;                    // local row 0..31
        int q  = rm & 127;                   // float4 index 0..127
        int p  = jcta * 32 + rl;
        int orig = ((p & 3) << 9) | (p >> 2);
        float4 v = *(const float4*)(Whh + ((size_t)l * G4 + orig) * Dd + q * 4);
        float* d = Bs + (l * 32 + rl) * 516 + q * 4;
        d[0] = v.x; d[1] = v.y; d[2] = v.z; d[3] = v.w;
    }
    for (int i = tid; i < 64 * 8; i += 256) csm[i >> 3][i & 7] = 0.f;
    // cache LN params for this CTA's LN row
    float lg0 = lng[tid], lg1 = lng[tid + 256];
    float lb0 = lnb[tid], lb1 = lnb[tid + 256];
    __syncthreads();

    const int arow = tid >> 2, acb = tid & 3;   // A-load assignment

    for (int t = 0; t < Tt; t++) {
#pragma unroll 1
        for (int l = 0; l < 2; l++) {
            const float* A    = (l == 0) ? g_h : g_hm;
            const float* gx   = g_Gx + ((size_t)l * Tt + t) * Bn * G4;
            float*       hout = (l == 0) ? g_hm : g_hr;
            const float* Bsl  = Bs + l * 32 * 516;

            float accA[2][4], accB[2][4];
#pragma unroll
            for (int n = 0; n < 2; n++)
#pragma unroll
                for (int q = 0; q < 4; q++) { accA[n][q] = 0.f; accB[n][q] = 0.f; }

            // prefetch chunk 0, store to buf 0
            float4 av = *(const float4*)(A + (size_t)(bm0 + arow) * Dd + acb * 4);
            {
                unsigned h0 = f2t(av.x), h1 = f2t(av.y), h2 = f2t(av.z), h3 = f2t(av.w);
                Ah[0][acb * 4 + 0][arow] = h0; Al[0][acb * 4 + 0][arow] = f2t(av.x - __uint_as_float(h0));
                Ah[0][acb * 4 + 1][arow] = h1; Al[0][acb * 4 + 1][arow] = f2t(av.y - __uint_as_float(h1));
                Ah[0][acb * 4 + 2][arow] = h2; Al[0][acb * 4 + 2][arow] = f2t(av.z - __uint_as_float(h2));
                Ah[0][acb * 4 + 3][arow] = h3; Al[0][acb * 4 + 3][arow] = f2t(av.w - __uint_as_float(h3));
            }
            av = *(const float4*)(A + (size_t)(bm0 + arow) * Dd + 16 + acb * 4);
            __syncthreads();

#pragma unroll 1
            for (int i = 0; i < 32; i++) {
                const int cur = i & 1;
                // stage chunk i+1 into other buffer; prefetch chunk i+2
                if (i < 31) {
                    const int nxt = cur ^ 1;
                    unsigned h0 = f2t(av.x), h1 = f2t(av.y), h2 = f2t(av.z), h3 = f2t(av.w);
                    Ah[nxt][acb * 4 + 0][arow] = h0; Al[nxt][acb * 4 + 0][arow] = f2t(av.x - __uint_as_float(h0));
                    Ah[nxt][acb * 4 + 1][arow] = h1; Al[nxt][acb * 4 + 1][arow] = f2t(av.y - __uint_as_float(h1));
                    Ah[nxt][acb * 4 + 2][arow] = h2; Al[nxt][acb * 4 + 2][arow] = f2t(av.z - __uint_as_float(h2));
                    Ah[nxt][acb * 4 + 3][arow] = h3; Al[nxt][acb * 4 + 3][arow] = f2t(av.w - __uint_as_float(h3));
                    if (i < 30)
                        av = *(const float4*)(A + (size_t)(bm0 + arow) * Dd + (i + 2) * 16 + acb * 4);
                }
                const int k0 = i * 16;
                const int mm = wm * 16 + gid;
#pragma unroll
                for (int ks = 0; ks < 2; ks++) {
                    const int kb = ks * 8;
                    unsigned ah[4], al[4];
                    ah[0] = Ah[cur][kb + t4    ][mm];
                    ah[1] = Ah[cur][kb + t4    ][mm + 8];
                    ah[2] = Ah[cur][kb + t4 + 4][mm];
                    ah[3] = Ah[cur][kb + t4 + 4][mm + 8];
                    al[0] = Al[cur][kb + t4    ][mm];
                    al[1] = Al[cur][kb + t4    ][mm + 8];
                    al[2] = Al[cur][kb + t4 + 4][mm];
                    al[3] = Al[cur][kb + t4 + 4][mm + 8];
#pragma unroll
                    for (int nf = 0; nf < 2; nf++) {
                        const int nn = wn * 16 + nf * 8 + gid;
                        float b0 = Bsl[nn * 516 + k0 + kb + t4];
                        float b1 = Bsl[nn * 516 + k0 + kb + t4 + 4];
                        unsigned bh[2], bl[2];
                        bh[0] = f2t(b0); bl[0] = f2t(b0 - __uint_as_float(bh[0]));
                        bh[1] = f2t(b1); bl[1] = f2t(b1 - __uint_as_float(bh[1]));
                        mma_tf32(accA[nf], ah, bh);
                        mma_tf32(accB[nf], al, bh);
                        mma_tf32(accB[nf], ah, bl);
                    }
                }
                __syncthreads();
            }
            // accumulators -> Cs (unions staging; safe after last sync)
#pragma unroll
            for (int nf = 0; nf < 2; nf++) {
                int r0 = wm * 16 + gid;
                int c0 = wn * 16 + nf * 8 + 2 * t4;
                Cs[r0    ][c0    ] = accA[nf][0] + accB[nf][0];
                Cs[r0    ][c0 + 1] = accA[nf][1] + accB[nf][1];
                Cs[r0 + 8][c0    ] = accA[nf][2] + accB[nf][2];
                Cs[r0 + 8][c0 + 1] = accA[nf][3] + accB[nf][3];
            }
            __syncthreads();
            // LSTM cell: 64x8 = 512 elements, 2 per thread
#pragma unroll
            for (int it = 0; it < 2; it++) {
                int x    = tid + it * 256;
                int brow = x >> 3, jj = x & 7;
                int b    = bm0 + brow;
                int j    = jcta * 8 + jj;
                float gi = Cs[brow][jj * 4 + 0] + gx[b * G4 + j];
                float gf = Cs[brow][jj * 4 + 1] + gx[b * G4 + 512 + j];
                float gg = Cs[brow][jj * 4 + 2] + gx[b * G4 + 1024 + j];
                float go = Cs[brow][jj * 4 + 3] + gx[b * G4 + 1536 + j];
                float ii = 1.f / (1.f + expf(-gi));
                float ff = 1.f / (1.f + expf(-gf));
                float gt = tanhf(gg);
                float oo = 1.f / (1.f + expf(-go));
                float cn = ff * csm[brow][jj] + ii * gt;
                csm[brow][jj] = cn;
                hout[(size_t)b * Dd + j] = oo * tanhf(cn);
            }
            grid_barrier(target);
        }
        // ---- LayerNorm: CTA handles batch row b = cta (256 threads, 2 elems) --
        {
            const float* xr = g_hr + (size_t)cta * Dd;
            float v0 = xr[tid], v1 = xr[tid + 256];
            float s = v0 + v1;
#pragma unroll
            for (int o = 16; o > 0; o >>= 1) s += __shfl_xor_sync(0xffffffffu, s, o);
            if (lane == 0) red[warp] = s;
            __syncthreads();
            float mu = (red[0] + red[1] + red[2] + red[3] +
                        red[4] + red[5] + red[6] + red[7]) * (1.f / 512.f);
            __syncthreads();
            float d0 = v0 - mu, d1 = v1 - mu;
            float vv = d0 * d0 + d1 * d1;
#pragma unroll
            for (int o = 16; o > 0; o >>= 1) vv += __shfl_xor_sync(0xffffffffu, vv, o);
            if (lane == 0) red[warp] = vv;
            __syncthreads();
            float var  = (red[0] + red[1] + red[2] + red[3] +
                          red[4] + red[5] + red[6] + red[7]) * (1.f / 512.f);
            float rstd = rsqrtf(var + 1e-5f);
            float y0 = d0 * rstd * lg0 + lb0;
            float y1 = d1 * rstd * lg1 + lb1;
            g_h[(size_t)cta * Dd + tid]       = y0;
            g_h[(size_t)cta * Dd + tid + 256] = y1;
            if (t > 0) {
                g_H[((size_t)(t - 1) * Bn + cta) * Dd + tid]       = y0;
                g_H[((size_t)(t - 1) * Bn + cta) * Dd + tid + 256] = y1;
            }
            __syncthreads();
        }
        grid_barrier(target);
    }
}

// ---------------- generic GEMM: C = A(MxK) * B(NxK)^T ------------------------
// EPI 0: C[m][n] = acc + bias1[n] + bias2[n]               (Gx precompute)
// EPI 1: FC store with row permutation (m = (t-1)*128+b -> out row b*32+(t-1))
// PREC 1: single tf32. PREC 3: tf32x3 split precision.
// 2-stage register prefetch on the global loads.
template<int BM, int BN, int WM, int WN, int EPI, int PREC>
__global__ void __launch_bounds__(WM * WN * 32)
gemm_tf32(const float* __restrict__ A, int M, int lda,
          const float* __restrict__ Bm, int N, int ldb, int K,
          const float* __restrict__ bias1, const float* __restrict__ bias2,
          float* __restrict__ C, int ldc)
{
    constexpr int THREADS = WM * WN * 32;
    constexpr int PAD = 4;
    constexpr int MF = 2, NF = 4;              // warp tile 32x32

    __shared__ unsigned Ash[16][BM + PAD];
    __shared__ unsigned Bsh[16][BN + PAD];
    __shared__ unsigned Asl[(PREC == 3) ? 16 : 1][BM + PAD];
    __shared__ unsigned Bsl[(PREC == 3) ? 16 : 1][BN + PAD];

    const int tid  = threadIdx.x;
    const int lane = tid & 31;
    const int warp = tid >> 5;
    const int wn = warp % WN, wm = warp / WN;
    const int gid = lane >> 2, t4 = lane & 3;
    const int m0 = blockIdx.x * BM;
    const int n0 = blockIdx.y * BN;

    float acc[MF][NF][4];
#pragma unroll
    for (int i = 0; i < MF; i++)
#pragma unroll
        for (int j = 0; j < NF; j++)
#pragma unroll
            for (int q = 0; q < 4; q++) acc[i][j][q] = 0.f;

    constexpr int LA = (BM * 16) / (THREADS * 4);
    constexpr int LB = (BN * 16) / (THREADS * 4);

    float4 ra[LA], rb[LB];

#define LOAD_T(K0)                                                          \
    {                                                                       \
        _Pragma("unroll")                                                   \
        for (int i = 0; i < LA; i++) {                                      \
            int f4 = tid + i * THREADS;                                     \
            int row = f4 >> 2, cb = f4 & 3;                                 \
            int gm = m0 + row;                                              \
            ra[i] = make_float4(0.f, 0.f, 0.f, 0.f);                        \
            if (gm < M) ra[i] = *(const float4*)(A + (size_t)gm * lda + (K0) + cb * 4); \
        }                                                                   \
        _Pragma("unroll")                                                   \
        for (int i = 0; i < LB; i++) {                                      \
            int f4 = tid + i * THREADS;                                     \
            int row = f4 >> 2, cb = f4 & 3;                                 \
            int grow = n0 + row;                                            \
            rb[i] = make_float4(0.f, 0.f, 0.f, 0.f);                        \
            if (grow < N) rb[i] = *(const float4*)(Bm + (size_t)grow * ldb + (K0) + cb * 4); \
        }                                                                   \
    }

#define SPLIT_STORE(AH, AL, KK, IDX, VAL)                               \
    { unsigned h_ = f2t(VAL); AH[KK][IDX] = h_;                         \
      if (PREC == 3) AL[KK][IDX] = f2t((VAL) - __uint_as_float(h_)); }

    LOAD_T(0)

    for (int k0 = 0; k0 < K; k0 += 16) {
#pragma unroll
        for (int i = 0; i < LA; i++) {
            int f4 = tid + i * THREADS;
            int row = f4 >> 2, cb = f4 & 3;
            SPLIT_STORE(Ash, Asl, cb * 4 + 0, row, ra[i].x);
            SPLIT_STORE(Ash, Asl, cb * 4 + 1, row, ra[i].y);
            SPLIT_STORE(Ash, Asl, cb * 4 + 2, row, ra[i].z);
            SPLIT_STORE(Ash, Asl, cb * 4 + 3, row, ra[i].w);
        }
#pragma unroll
        for (int i = 0; i < LB; i++) {
            int f4 = tid + i * THREADS;
            int row = f4 >> 2, cb = f4 & 3;
            SPLIT_STORE(Bsh, Bsl, cb * 4 + 0, row, rb[i].x);
            SPLIT_STORE(Bsh, Bsl, cb * 4 + 1, row, rb[i].y);
            SPLIT_STORE(Bsh, Bsl, cb * 4 + 2, row, rb[i].z);
            SPLIT_STORE(Bsh, Bsl, cb * 4 + 3, row, rb[i].w);
        }
        __syncthreads();

        if (k0 + 16 < K) LOAD_T(k0 + 16)

#pragma unroll
        for (int ks = 0; ks < 2; ks++) {
            const int kb = ks * 8;
            unsigned ah[MF][4], al[MF][4], bh[NF][2], bl[NF][2];
#pragma unroll
            for (int mf = 0; mf < MF; mf++) {
                int mm = wm * 32 + mf * 16 + gid;
                ah[mf][0] = Ash[kb + t4    ][mm];
                ah[mf][1] = Ash[kb + t4    ][mm + 8];
                ah[mf][2] = Ash[kb + t4 + 4][mm];
                ah[mf][3] = Ash[kb + t4 + 4][mm + 8];
                if (PREC == 3) {
                    al[mf][0] = Asl[kb + t4    ][mm];
                    al[mf][1] = Asl[kb + t4    ][mm + 8];
                    al[mf][2] = Asl[kb + t4 + 4][mm];
                    al[mf][3] = Asl[kb + t4 + 4][mm + 8];
                }
            }
#pragma unroll
            for (int nf = 0; nf < NF; nf++) {
                int nn = wn * 32 + nf * 8 + gid;
                bh[nf][0] = Bsh[kb + t4    ][nn];
                bh[nf][1] = Bsh[kb + t4 + 4][nn];
                if (PREC == 3) {
                    bl[nf][0] = Bsl[kb + t4    ][nn];
                    bl[nf][1] = Bsl[kb + t4 + 4][nn];
                }
            }
#pragma unroll
            for (int mf = 0; mf < MF; mf++)
#pragma unroll
                for (int nf = 0; nf < NF; nf++) {
                    mma_tf32(acc[mf][nf], ah[mf], bh[nf]);
                    if (PREC == 3) {
                        mma_tf32(acc[mf][nf], al[mf], bh[nf]);
                        mma_tf32(acc[mf][nf], ah[mf], bl[nf]);
                    }
                }
        }
        __syncthreads();
    }

#pragma unroll
    for (int mf = 0; mf < MF; mf++)
#pragma unroll
        for (int nf = 0; nf < NF; nf++) {
            int r0 = m0 + wm * 32 + mf * 16 + gid;
            int c0 = n0 + wn * 32 + nf * 8 + 2 * t4;
#pragma unroll
            for (int q = 0; q < 4; q++) {
                int r = r0 + ((q >= 2) ? 8 : 0);
                int c = c0 + (q & 1);
                if (r < M && c < N) {
                    float v = acc[mf][nf][q];
                    if (bias1) v += bias1[c];
                    if (bias2) v += bias2[c];
                    if (EPI == 0) {
                        C[(size_t)r * ldc + c] = v;
                    } else {
                        int orow = (r & 127) * Ll + (r >> 7);
                        C[(size_t)orow * ldc + c] = v;
                    }
                }
            }
        }
#undef SPLIT_STORE
#undef LOAD_T
}

// ---------------- in-place log_softmax, rows of 10000 ------------------------
__global__ void k_lsm(float* __restrict__ out) {
    __shared__ float row[Vv];
    __shared__ float red[8];
    float* p = out + (size_t)blockIdx.x * Vv;
    int tid = threadIdx.x;            // 256 threads

    float mx = -1e30f;
    float4*       r4 = (float4*)row;
    const float4* p4 = (const float4*)p;
    for (int i = tid; i < Vv / 4; i += 256) {
        float4 v = p4[i];
        r4[i] = v;
        mx = fmaxf(mx, fmaxf(fmaxf(v.x, v.y), fmaxf(v.z, v.w)));
    }
#pragma unroll
    for (int o = 16; o > 0; o >>= 1) mx = fmaxf(mx, __shfl_xor_sync(0xffffffffu, mx, o));
    if ((tid & 31) == 0) red[tid >> 5] = mx;
    __syncthreads();
    mx = red[0];
#pragma unroll
    for (int i = 1; i < 8; i++) mx = fmaxf(mx, red[i]);

    float s = 0.f;
    for (int i = tid; i < Vv; i += 256) s += expf(row[i] - mx);
#pragma unroll
    for (int o = 16; o > 0; o >>= 1) s += __shfl_xor_sync(0xffffffffu, s, o);
    __syncthreads();
    if ((tid & 31) == 0) red[tid >> 5] = s;
    __syncthreads();
    s = red[0] + red[1] + red[2] + red[3] + red[4] + red[5] + red[6] + red[7];
    float lse = mx + logf(s);

    for (int i = tid; i < Vv; i += 256) p[i] = row[i] - lse;
}

// ---------------- host launcher ----------------------------------------------
extern "C" void kernel_launch(void* const* d_in, const int* in_sizes, int n_in,
                              void* d_out, int out_size) {
    const float* features = (const float*)d_in[0];
    const void*  caption  = d_in[1];
    const float* embW     = (const float*)d_in[2];
    const float* Wih      = (const float*)d_in[3];
    const float* Whh      = (const float*)d_in[4];
    const float* bih      = (const float*)d_in[5];
    const float* bhh      = (const float*)d_in[6];
    const float* lng      = (const float*)d_in[7];
    const float* lnb      = (const float*)d_in[8];
    const float* fcW      = (const float*)d_in[9];
    const float* fcb      = (const float*)d_in[10];
    float*       out      = (float*)d_out;

    float *pX, *pGx, *pH;
    cudaGetSymbolAddress((void**)&pX,  g_X);
    cudaGetSymbolAddress((void**)&pGx, g_Gx);
    cudaGetSymbolAddress((void**)&pH,  g_H);

    cudaFuncSetAttribute(k_recurrence,
                         cudaFuncAttributeMaxDynamicSharedMemorySize, SMEM_REC);

    k_init<<<256, 256>>>();
    k_detect<<<1, 256>>>((const int*)caption);
    k_build_x<<<Tt * Bn, 128>>>(features, caption, embW);

    // Gx = X @ Wih^T + bih + bhh   (both layers, tf32x3)
    for (int l = 0; l < 2; l++)
        gemm_tf32<128, 64, 4, 2, 0, 3><<<dim3(33, 32), 256>>>(
            pX, Tt * Bn, Dd,
            Wih + (size_t)l * G4 * Dd, G4, Dd, Dd,
            bih + l * G4, bhh + l * G4,
            pGx + (size_t)l * Tt * Bn * G4, G4);

    // full 33-step recurrence in ONE persistent kernel (single wave)
    k_recurrence<<<128, 256, SMEM_REC>>>(Whh, lng, lnb);

    // FC: logits = H @ fcW^T + fcb  (single tf32, permuted store)
    gemm_tf32<128, 64, 4, 2, 1, 1><<<dim3(32, 157), 256>>>(
        pH, Ll * Bn, Dd, fcW, Vv, Dd, Dd,
        fcb, nullptr, out, Vv);

    k_lsm<<<Ll * Bn, 256>>>(out);
}

// round 6
// speedup vs baseline: 1.7845x; 1.1474x over previous
#include <cuda_runtime.h>
#include <math.h>
#include <stdint.h>

#define Bn   128
#define Dd   512
#define Tt   33
#define Ll   32
#define Vv   10000
#define G4   2048

// ---------------- static device scratch ------------------------------------
__device__ float    g_X  [Tt * Bn * Dd];        // per-step inputs
__device__ float    g_Gx [2 * Tt * Bn * G4];    // x-side gates (both layers)
__device__ float    g_H  [Ll * Bn * Dd];        // normalized h history
__device__ float    g_h  [Bn * Dd];             // carried h (normalized)
__device__ float    g_hm [Bn * Dd];             // h after layer 0
__device__ float    g_hr [Bn * Dd];             // h after layer 1 (pre-LN)
__device__ unsigned g_bar;                      // grid barrier counter
__device__ int      g_cap64;

// ---------------- utility kernels -------------------------------------------
__global__ void k_init() {
    int i = blockIdx.x * blockDim.x + threadIdx.x;
    if (i < Bn * Dd) g_h[i] = 0.f;
    if (i == 0) g_bar = 0u;
}

// caption int64 vs int32 detection (values < 10000 => int64 high words all 0)
__global__ void k_detect(const int* __restrict__ cap) {
    int any = 0;
    for (int i = threadIdx.x; i < 2048; i += blockDim.x)
        if (cap[2 * i + 1] != 0) any = 1;
    any = __syncthreads_or(any);
    if (threadIdx.x == 0) g_cap64 = any ? 0 : 1;
}

__global__ void k_build_x(const float* __restrict__ features,
                          const void*  __restrict__ cap,
                          const float* __restrict__ embW) {
    int blk = blockIdx.x;
    int t = blk >> 7;
    int b = blk & 127;
    const float* src;
    if (t == 0) {
        src = features + (size_t)b * Dd;
    } else {
        long long idx;
        if (g_cap64) idx = ((const long long*)cap)[b * Ll + (t - 1)];
        else         idx = (long long)((const int*)cap)[b * Ll + (t - 1)];
        src = embW + (size_t)idx * Dd;
    }
    float4*       dst = (float4*)(g_X + ((size_t)t * Bn + b) * Dd);
    const float4* s4  = (const float4*)src;
    dst[threadIdx.x] = s4[threadIdx.x];
}

// ---------------- tf32 helpers (Gx / FC path) --------------------------------
__device__ __forceinline__ unsigned f2t(float x) {
    unsigned r;
    asm("cvt.rna.tf32.f32 %0, %1;" : "=r"(r) : "f"(x));
    return r;
}

__device__ __forceinline__ void mma_tf32(float* c, const unsigned* a, const unsigned* b) {
    asm volatile(
        "mma.sync.aligned.m16n8k8.row.col.f32.tf32.tf32.f32 "
        "{%0,%1,%2,%3}, {%4,%5,%6,%7}, {%8,%9}, {%0,%1,%2,%3};\n"
        : "+f"(c[0]), "+f"(c[1]), "+f"(c[2]), "+f"(c[3])
        : "r"(a[0]), "r"(a[1]), "r"(a[2]), "r"(a[3]), "r"(b[0]), "r"(b[1]));
}

// ---------------- bf16 helpers (recurrence path) ------------------------------
// pack: e0 -> low half, e1 -> high half
__device__ __forceinline__ unsigned bpack(float e0, float e1) {
    unsigned r;
    asm("cvt.rn.bf16x2.f32 %0, %1, %2;" : "=r"(r) : "f"(e1), "f"(e0));
    return r;
}
__device__ __forceinline__ float blo(unsigned p) { return __uint_as_float(p << 16); }
__device__ __forceinline__ float bhi(unsigned p) { return __uint_as_float(p & 0xffff0000u); }

__device__ __forceinline__ void mma_bf16(float* c,
                                         unsigned a0, unsigned a1, unsigned a2, unsigned a3,
                                         unsigned b0, unsigned b1) {
    asm volatile(
        "mma.sync.aligned.m16n8k16.row.col.f32.bf16.bf16.f32 "
        "{%0,%1,%2,%3}, {%4,%5,%6,%7}, {%8,%9}, {%0,%1,%2,%3};\n"
        : "+f"(c[0]), "+f"(c[1]), "+f"(c[2]), "+f"(c[3])
        : "r"(a0), "r"(a1), "r"(a2), "r"(a3), "r"(b0), "r"(b1));
}

// ---------------- grid barrier (persistent kernel, single wave) -------------
__device__ __forceinline__ void grid_barrier(unsigned& target) {
    __syncthreads();
    if (threadIdx.x == 0) {
        target += gridDim.x;
        __threadfence();
        atomicAdd(&g_bar, 1u);
        while (*((volatile unsigned*)&g_bar) < target) { }
        __threadfence();
    }
    __syncthreads();
}

// ---------------- persistent recurrence kernel -------------------------------
// 128 CTAs x 256 threads = 2 batch-groups (64 rows) x 64 j-groups (8 cols).
// Whh slice (both layers) pre-split to bf16 hi/lo pairs, resident in smem.
// A (h) staged per half-K as bf16 hi/lo pairs. bf16x3 mma (hi.hi+lo.hi+hi.lo).
// smem layout (dynamic, bytes):
//   Bsm  uint2[2*32][258]   0      .. 132096   (kp pairs, {hi,lo})
//   Asm  uint2[128][66]     132096 .. 199680   (half-K staging)
//   Cs   float[64][36]      199680 .. 208896
//   csm  float[64][8]       208896 .. 210944
//   red  float[8]           210944 .. 210976
#define SMEM_REC 210976
__global__ void __launch_bounds__(256, 1)
k_recurrence(const float* __restrict__ Whh,
             const float* __restrict__ lng, const float* __restrict__ lnb) {
    extern __shared__ __align__(16) char sbuf[];
    uint2* Bsm          = (uint2*)sbuf;                      // [(l*32+row)*258 + kp]
    uint2 (*Asm)[66]    = (uint2(*)[66])(sbuf + 132096);     // [kp][row]
    float (*Cs)[36]     = (float(*)[36])(sbuf + 199680);
    float (*csm)[8]     = (float(*)[8])(sbuf + 208896);
    float* red          = (float*)(sbuf + 210944);

    const int tid  = threadIdx.x;
    const int lane = tid & 31;
    const int warp = tid >> 5;
    const int gid  = lane >> 2, t4 = lane & 3;
    const int cta  = blockIdx.x;             // 0..127
    const int jcta = cta & 63;               // j-group: cols [jcta*8, jcta*8+8)
    const int bm0  = (cta >> 6) * 64;        // batch-group base row
    const int wm   = warp >> 1, wn = warp & 1;  // 4x2 warps, warp tile 16x16
    unsigned target = 0;

    // ---- one-time: load + bf16-split this CTA's Whh slice (both layers) ----
    // interleaved row p = jcta*32 + rl  <->  original row ((p&3)<<9) | (p>>2)
    for (int idx = tid; idx < 2 * 32 * 256; idx += 256) {
        int l  = idx >> 13;
        int rm = idx & 8191;
        int rl = rm >> 8;                    // local row 0..31
        int kp = rm & 255;                   // k-pair 0..255
        int p  = jcta * 32 + rl;
        int orig = ((p & 3) << 9) | (p >> 2);
        float2 v = *(const float2*)(Whh + ((size_t)l * G4 + orig) * Dd + kp * 2);
        unsigned h = bpack(v.x, v.y);
        unsigned lo = bpack(v.x - blo(h), v.y - bhi(h));
        Bsm[(l * 32 + rl) * 258 + kp] = make_uint2(h, lo);
    }
    for (int i = tid; i < 64 * 8; i += 256) csm[i >> 3][i & 7] = 0.f;
    // cache LN params for this CTA's LN row
    float lg0 = lng[tid], lg1 = lng[tid + 256];
    float lb0 = lnb[tid], lb1 = lnb[tid + 256];
    __syncthreads();

    for (int t = 0; t < Tt; t++) {
#pragma unroll 1
        for (int l = 0; l < 2; l++) {
            const float* A    = (l == 0) ? g_h : g_hm;
            const float* gx   = g_Gx + ((size_t)l * Tt + t) * Bn * G4;
            float*       hout = (l == 0) ? g_hm : g_hr;
            const int    l32  = l * 32;

            float accA[2][4], accB[2][4];
#pragma unroll
            for (int n = 0; n < 2; n++)
#pragma unroll
                for (int q = 0; q < 4; q++) { accA[n][q] = 0.f; accB[n][q] = 0.f; }

#pragma unroll 1
            for (int half = 0; half < 2; half++) {
                // ---- stage A half: 64 rows x 256 k -> bf16 hi/lo pairs ----
                const float* Ag = A + (size_t)bm0 * Dd + half * 256;
#pragma unroll
                for (int r = 0; r < 16; r++) {
                    int idx = tid + r * 256;
                    int row = idx >> 6, c4 = idx & 63;
                    float4 v = *(const float4*)(Ag + (size_t)row * Dd + c4 * 4);
                    unsigned h01 = bpack(v.x, v.y);
                    unsigned h23 = bpack(v.z, v.w);
                    unsigned l01 = bpack(v.x - blo(h01), v.y - bhi(h01));
                    unsigned l23 = bpack(v.z - blo(h23), v.w - bhi(h23));
                    Asm[c4 * 2    ][row] = make_uint2(h01, l01);
                    Asm[c4 * 2 + 1][row] = make_uint2(h23, l23);
                }
                __syncthreads();

                const int mm = wm * 16 + gid;
                const int kpb = half * 128;
#pragma unroll
                for (int i = 0; i < 16; i++) {
                    uint2 a0 = Asm[i * 8 + t4    ][mm];
                    uint2 a1 = Asm[i * 8 + t4    ][mm + 8];
                    uint2 a2 = Asm[i * 8 + t4 + 4][mm];
                    uint2 a3 = Asm[i * 8 + t4 + 4][mm + 8];
#pragma unroll
                    for (int nf = 0; nf < 2; nf++) {
                        int nn = wn * 16 + nf * 8 + gid;
                        uint2 b0 = Bsm[(l32 + nn) * 258 + kpb + i * 8 + t4    ];
                        uint2 b1 = Bsm[(l32 + nn) * 258 + kpb + i * 8 + t4 + 4];
                        mma_bf16(accA[nf], a0.x, a1.x, a2.x, a3.x, b0.x, b1.x);  // hi.hi
                        mma_bf16(accB[nf], a0.y, a1.y, a2.y, a3.y, b0.x, b1.x);  // lo.hi
                        mma_bf16(accB[nf], a0.x, a1.x, a2.x, a3.x, b0.y, b1.y);  // hi.lo
                    }
                }
                __syncthreads();
            }
            // accumulators -> Cs
#pragma unroll
            for (int nf = 0; nf < 2; nf++) {
                int r0 = wm * 16 + gid;
                int c0 = wn * 16 + nf * 8 + 2 * t4;
                Cs[r0    ][c0    ] = accA[nf][0] + accB[nf][0];
                Cs[r0    ][c0 + 1] = accA[nf][1] + accB[nf][1];
                Cs[r0 + 8][c0    ] = accA[nf][2] + accB[nf][2];
                Cs[r0 + 8][c0 + 1] = accA[nf][3] + accB[nf][3];
            }
            __syncthreads();
            // LSTM cell: 64x8 = 512 elements, 2 per thread
#pragma unroll
            for (int it = 0; it < 2; it++) {
                int x    = tid + it * 256;
                int brow = x >> 3, jj = x & 7;
                int b    = bm0 + brow;
                int j    = jcta * 8 + jj;
                float gi = Cs[brow][jj * 4 + 0] + gx[b * G4 + j];
                float gf = Cs[brow][jj * 4 + 1] + gx[b * G4 + 512 + j];
                float gg = Cs[brow][jj * 4 + 2] + gx[b * G4 + 1024 + j];
                float go = Cs[brow][jj * 4 + 3] + gx[b * G4 + 1536 + j];
                float ii = 1.f / (1.f + expf(-gi));
                float ff = 1.f / (1.f + expf(-gf));
                float gt = tanhf(gg);
                float oo = 1.f / (1.f + expf(-go));
                float cn = ff * csm[brow][jj] + ii * gt;
                csm[brow][jj] = cn;
                hout[(size_t)b * Dd + j] = oo * tanhf(cn);
            }
            grid_barrier(target);
        }
        // ---- LayerNorm: CTA handles batch row b = cta (256 threads, 2 elems) --
        {
            const float* xr = g_hr + (size_t)cta * Dd;
            float v0 = xr[tid], v1 = xr[tid + 256];
            float s = v0 + v1;
#pragma unroll
            for (int o = 16; o > 0; o >>= 1) s += __shfl_xor_sync(0xffffffffu, s, o);
            if (lane == 0) red[warp] = s;
            __syncthreads();
            float mu = (red[0] + red[1] + red[2] + red[3] +
                        red[4] + red[5] + red[6] + red[7]) * (1.f / 512.f);
            __syncthreads();
            float d0 = v0 - mu, d1 = v1 - mu;
            float vv = d0 * d0 + d1 * d1;
#pragma unroll
            for (int o = 16; o > 0; o >>= 1) vv += __shfl_xor_sync(0xffffffffu, vv, o);
            if (lane == 0) red[warp] = vv;
            __syncthreads();
            float var  = (red[0] + red[1] + red[2] + red[3] +
                          red[4] + red[5] + red[6] + red[7]) * (1.f / 512.f);
            float rstd = rsqrtf(var + 1e-5f);
            float y0 = d0 * rstd * lg0 + lb0;
            float y1 = d1 * rstd * lg1 + lb1;
            g_h[(size_t)cta * Dd + tid]       = y0;
            g_h[(size_t)cta * Dd + tid + 256] = y1;
            if (t > 0) {
                g_H[((size_t)(t - 1) * Bn + cta) * Dd + tid]       = y0;
                g_H[((size_t)(t - 1) * Bn + cta) * Dd + tid + 256] = y1;
            }
            __syncthreads();
        }
        grid_barrier(target);
    }
}

// ---------------- generic GEMM: C = A(MxK) * B(NxK)^T ------------------------
// EPI 0: C[m][n] = acc + bias1[n] + bias2[n]               (Gx precompute)
// EPI 1: FC store with row permutation (m = (t-1)*128+b -> out row b*32+(t-1))
// PREC 1: single tf32. PREC 3: tf32x3 split precision.
// 2-stage register prefetch on the global loads.
template<int BM, int BN, int WM, int WN, int EPI, int PREC>
__global__ void __launch_bounds__(WM * WN * 32)
gemm_tf32(const float* __restrict__ A, int M, int lda,
          const float* __restrict__ Bm, int N, int ldb, int K,
          const float* __restrict__ bias1, const float* __restrict__ bias2,
          float* __restrict__ C, int ldc)
{
    constexpr int THREADS = WM * WN * 32;
    constexpr int PAD = 4;
    constexpr int MF = 2, NF = 4;              // warp tile 32x32

    __shared__ unsigned Ash[16][BM + PAD];
    __shared__ unsigned Bsh[16][BN + PAD];
    __shared__ unsigned Asl[(PREC == 3) ? 16 : 1][BM + PAD];
    __shared__ unsigned Bsl[(PREC == 3) ? 16 : 1][BN + PAD];

    const int tid  = threadIdx.x;
    const int lane = tid & 31;
    const int warp = tid >> 5;
    const int wn = warp % WN, wm = warp / WN;
    const int gid = lane >> 2, t4 = lane & 3;
    const int m0 = blockIdx.x * BM;
    const int n0 = blockIdx.y * BN;

    float acc[MF][NF][4];
#pragma unroll
    for (int i = 0; i < MF; i++)
#pragma unroll
        for (int j = 0; j < NF; j++)
#pragma unroll
            for (int q = 0; q < 4; q++) acc[i][j][q] = 0.f;

    constexpr int LA = (BM * 16) / (THREADS * 4);
    constexpr int LB = (BN * 16) / (THREADS * 4);

    float4 ra[LA], rb[LB];

#define LOAD_T(K0)                                                          \
    {                                                                       \
        _Pragma("unroll")                                                   \
        for (int i = 0; i < LA; i++) {                                      \
            int f4 = tid + i * THREADS;                                     \
            int row = f4 >> 2, cb = f4 & 3;                                 \
            int gm = m0 + row;                                              \
            ra[i] = make_float4(0.f, 0.f, 0.f, 0.f);                        \
            if (gm < M) ra[i] = *(const float4*)(A + (size_t)gm * lda + (K0) + cb * 4); \
        }                                                                   \
        _Pragma("unroll")                                                   \
        for (int i = 0; i < LB; i++) {                                      \
            int f4 = tid + i * THREADS;                                     \
            int row = f4 >> 2, cb = f4 & 3;                                 \
            int grow = n0 + row;                                            \
            rb[i] = make_float4(0.f, 0.f, 0.f, 0.f);                        \
            if (grow < N) rb[i] = *(const float4*)(Bm + (size_t)grow * ldb + (K0) + cb * 4); \
        }                                                                   \
    }

#define SPLIT_STORE(AH, AL, KK, IDX, VAL)                               \
    { unsigned h_ = f2t(VAL); AH[KK][IDX] = h_;                         \
      if (PREC == 3) AL[KK][IDX] = f2t((VAL) - __uint_as_float(h_)); }

    LOAD_T(0)

    for (int k0 = 0; k0 < K; k0 += 16) {
#pragma unroll
        for (int i = 0; i < LA; i++) {
            int f4 = tid + i * THREADS;
            int row = f4 >> 2, cb = f4 & 3;
            SPLIT_STORE(Ash, Asl, cb * 4 + 0, row, ra[i].x);
            SPLIT_STORE(Ash, Asl, cb * 4 + 1, row, ra[i].y);
            SPLIT_STORE(Ash, Asl, cb * 4 + 2, row, ra[i].z);
            SPLIT_STORE(Ash, Asl, cb * 4 + 3, row, ra[i].w);
        }
#pragma unroll
        for (int i = 0; i < LB; i++) {
            int f4 = tid + i * THREADS;
            int row = f4 >> 2, cb = f4 & 3;
            SPLIT_STORE(Bsh, Bsl, cb * 4 + 0, row, rb[i].x);
            SPLIT_STORE(Bsh, Bsl, cb * 4 + 1, row, rb[i].y);
            SPLIT_STORE(Bsh, Bsl, cb * 4 + 2, row, rb[i].z);
            SPLIT_STORE(Bsh, Bsl, cb * 4 + 3, row, rb[i].w);
        }
        __syncthreads();

        if (k0 + 16 < K) LOAD_T(k0 + 16)

#pragma unroll
        for (int ks = 0; ks < 2; ks++) {
            const int kb = ks * 8;
            unsigned ah[MF][4], al[MF][4], bh[NF][2], bl[NF][2];
#pragma unroll
            for (int mf = 0; mf < MF; mf++) {
                int mm = wm * 32 + mf * 16 + gid;
                ah[mf][0] = Ash[kb + t4    ][mm];
                ah[mf][1] = Ash[kb + t4    ][mm + 8];
                ah[mf][2] = Ash[kb + t4 + 4][mm];
                ah[mf][3] = Ash[kb + t4 + 4][mm + 8];
                if (PREC == 3) {
                    al[mf][0] = Asl[kb + t4    ][mm];
                    al[mf][1] = Asl[kb + t4    ][mm + 8];
                    al[mf][2] = Asl[kb + t4 + 4][mm];
                    al[mf][3] = Asl[kb + t4 + 4][mm + 8];
                }
            }
#pragma unroll
            for (int nf = 0; nf < NF; nf++) {
                int nn = wn * 32 + nf * 8 + gid;
                bh[nf][0] = Bsh[kb + t4    ][nn];
                bh[nf][1] = Bsh[kb + t4 + 4][nn];
                if (PREC == 3) {
                    bl[nf][0] = Bsl[kb + t4    ][nn];
                    bl[nf][1] = Bsl[kb + t4 + 4][nn];
                }
            }
#pragma unroll
            for (int mf = 0; mf < MF; mf++)
#pragma unroll
                for (int nf = 0; nf < NF; nf++) {
                    mma_tf32(acc[mf][nf], ah[mf], bh[nf]);
                    if (PREC == 3) {
                        mma_tf32(acc[mf][nf], al[mf], bh[nf]);
                        mma_tf32(acc[mf][nf], ah[mf], bl[nf]);
                    }
                }
        }
        __syncthreads();
    }

#pragma unroll
    for (int mf = 0; mf < MF; mf++)
#pragma unroll
        for (int nf = 0; nf < NF; nf++) {
            int r0 = m0 + wm * 32 + mf * 16 + gid;
            int c0 = n0 + wn * 32 + nf * 8 + 2 * t4;
#pragma unroll
            for (int q = 0; q < 4; q++) {
                int r = r0 + ((q >= 2) ? 8 : 0);
                int c = c0 + (q & 1);
                if (r < M && c < N) {
                    float v = acc[mf][nf][q];
                    if (bias1) v += bias1[c];
                    if (bias2) v += bias2[c];
                    if (EPI == 0) {
                        C[(size_t)r * ldc + c] = v;
                    } else {
                        int orow = (r & 127) * Ll + (r >> 7);
                        C[(size_t)orow * ldc + c] = v;
                    }
                }
            }
        }
#undef SPLIT_STORE
#undef LOAD_T
}

// ---------------- in-place log_softmax, rows of 10000 ------------------------
__global__ void k_lsm(float* __restrict__ out) {
    __shared__ float row[Vv];
    __shared__ float red[8];
    float* p = out + (size_t)blockIdx.x * Vv;
    int tid = threadIdx.x;            // 256 threads

    float mx = -1e30f;
    float4*       r4 = (float4*)row;
    const float4* p4 = (const float4*)p;
    for (int i = tid; i < Vv / 4; i += 256) {
        float4 v = p4[i];
        r4[i] = v;
        mx = fmaxf(mx, fmaxf(fmaxf(v.x, v.y), fmaxf(v.z, v.w)));
    }
#pragma unroll
    for (int o = 16; o > 0; o >>= 1) mx = fmaxf(mx, __shfl_xor_sync(0xffffffffu, mx, o));
    if ((tid & 31) == 0) red[tid >> 5] = mx;
    __syncthreads();
    mx = red[0];
#pragma unroll
    for (int i = 1; i < 8; i++) mx = fmaxf(mx, red[i]);

    float s = 0.f;
    for (int i = tid; i < Vv; i += 256) s += expf(row[i] - mx);
#pragma unroll
    for (int o = 16; o > 0; o >>= 1) s += __shfl_xor_sync(0xffffffffu, s, o);
    __syncthreads();
    if ((tid & 31) == 0) red[tid >> 5] = s;
    __syncthreads();
    s = red[0] + red[1] + red[2] + red[3] + red[4] + red[5] + red[6] + red[7];
    float lse = mx + logf(s);

    for (int i = tid; i < Vv; i += 256) p[i] = row[i] - lse;
}

// ---------------- host launcher ----------------------------------------------
extern "C" void kernel_launch(void* const* d_in, const int* in_sizes, int n_in,
                              void* d_out, int out_size) {
    const float* features = (const float*)d_in[0];
    const void*  caption  = d_in[1];
    const float* embW     = (const float*)d_in[2];
    const float* Wih      = (const float*)d_in[3];
    const float* Whh      = (const float*)d_in[4];
    const float* bih      = (const float*)d_in[5];
    const float* bhh      = (const float*)d_in[6];
    const float* lng      = (const float*)d_in[7];
    const float* lnb      = (const float*)d_in[8];
    const float* fcW      = (const float*)d_in[9];
    const float* fcb      = (const float*)d_in[10];
    float*       out      = (float*)d_out;

    float *pX, *pGx, *pH;
    cudaGetSymbolAddress((void**)&pX,  g_X);
    cudaGetSymbolAddress((void**)&pGx, g_Gx);
    cudaGetSymbolAddress((void**)&pH,  g_H);

    cudaFuncSetAttribute(k_recurrence,
                         cudaFuncAttributeMaxDynamicSharedMemorySize, SMEM_REC);

    k_init<<<256, 256>>>();
    k_detect<<<1, 256>>>((const int*)caption);
    k_build_x<<<Tt * Bn, 128>>>(features, caption, embW);

    // Gx = X @ Wih^T + bih + bhh   (both layers, tf32x3)
    for (int l = 0; l < 2; l++)
        gemm_tf32<128, 64, 4, 2, 0, 3><<<dim3(33, 32), 256>>>(
            pX, Tt * Bn, Dd,
            Wih + (size_t)l * G4 * Dd, G4, Dd, Dd,
            bih + l * G4, bhh + l * G4,
            pGx + (size_t)l * Tt * Bn * G4, G4);

    // full 33-step recurrence in ONE persistent kernel (single wave)
    k_recurrence<<<128, 256, SMEM_REC>>>(Whh, lng, lnb);

    // FC: logits = H @ fcW^T + fcb  (single tf32, permuted store)
    gemm_tf32<128, 64, 4, 2, 1, 1><<<dim3(32, 157), 256>>>(
        pH, Ll * Bn, Dd, fcW, Vv, Dd, Dd,
        fcb, nullptr, out, Vv);

    k_lsm<<<Ll * Bn, 256>>>(out);
}

// round 7
// speedup vs baseline: 2.0743x; 1.1624x over previous
#include <cuda_runtime.h>
#include <math.h>
#include <stdint.h>

#define Bn   128
#define Dd   512
#define Tt   33
#define Ll   32
#define Vv   10000
#define G4   2048

// ---------------- static device scratch ------------------------------------
__device__ float    g_X  [Tt * Bn * Dd];        // per-step inputs
__device__ float    g_Gx [2 * Tt * Bn * G4];    // x-side gates (both layers)
__device__ float    g_H  [Ll * Bn * Dd];        // normalized h history
__device__ float    g_h  [Bn * Dd];             // carried h (normalized)
__device__ float    g_hm [Bn * Dd];             // h after layer 0
__device__ float    g_hr [Bn * Dd];             // h after layer 1 (pre-LN)
__device__ unsigned g_bar;                      // grid barrier counter
__device__ int      g_cap64;

// ---------------- utility kernels -------------------------------------------
__global__ void k_init() {
    int i = blockIdx.x * blockDim.x + threadIdx.x;
    if (i < Bn * Dd) g_h[i] = 0.f;
    if (i == 0) g_bar = 0u;
}

// caption int64 vs int32 detection (values < 10000 => int64 high words all 0)
__global__ void k_detect(const int* __restrict__ cap) {
    int any = 0;
    for (int i = threadIdx.x; i < 2048; i += blockDim.x)
        if (cap[2 * i + 1] != 0) any = 1;
    any = __syncthreads_or(any);
    if (threadIdx.x == 0) g_cap64 = any ? 0 : 1;
}

__global__ void k_build_x(const float* __restrict__ features,
                          const void*  __restrict__ cap,
                          const float* __restrict__ embW) {
    int blk = blockIdx.x;
    int t = blk >> 7;
    int b = blk & 127;
    const float* src;
    if (t == 0) {
        src = features + (size_t)b * Dd;
    } else {
        long long idx;
        if (g_cap64) idx = ((const long long*)cap)[b * Ll + (t - 1)];
        else         idx = (long long)((const int*)cap)[b * Ll + (t - 1)];
        src = embW + (size_t)idx * Dd;
    }
    float4*       dst = (float4*)(g_X + ((size_t)t * Bn + b) * Dd);
    const float4* s4  = (const float4*)src;
    dst[threadIdx.x] = s4[threadIdx.x];
}

// ---------------- tf32 helpers (FC path) -------------------------------------
__device__ __forceinline__ unsigned f2t(float x) {
    unsigned r;
    asm("cvt.rna.tf32.f32 %0, %1;" : "=r"(r) : "f"(x));
    return r;
}

__device__ __forceinline__ void mma_tf32(float* c, const unsigned* a, const unsigned* b) {
    asm volatile(
        "mma.sync.aligned.m16n8k8.row.col.f32.tf32.tf32.f32 "
        "{%0,%1,%2,%3}, {%4,%5,%6,%7}, {%8,%9}, {%0,%1,%2,%3};\n"
        : "+f"(c[0]), "+f"(c[1]), "+f"(c[2]), "+f"(c[3])
        : "r"(a[0]), "r"(a[1]), "r"(a[2]), "r"(a[3]), "r"(b[0]), "r"(b[1]));
}

// ---------------- bf16 helpers -------------------------------------------------
// pack: e0 -> low half, e1 -> high half
__device__ __forceinline__ unsigned bpack(float e0, float e1) {
    unsigned r;
    asm("cvt.rn.bf16x2.f32 %0, %1, %2;" : "=r"(r) : "f"(e1), "f"(e0));
    return r;
}
__device__ __forceinline__ float blo(unsigned p) { return __uint_as_float(p << 16); }
__device__ __forceinline__ float bhi(unsigned p) { return __uint_as_float(p & 0xffff0000u); }

__device__ __forceinline__ void mma_bf16(float* c,
                                         unsigned a0, unsigned a1, unsigned a2, unsigned a3,
                                         unsigned b0, unsigned b1) {
    asm volatile(
        "mma.sync.aligned.m16n8k16.row.col.f32.bf16.bf16.f32 "
        "{%0,%1,%2,%3}, {%4,%5,%6,%7}, {%8,%9}, {%0,%1,%2,%3};\n"
        : "+f"(c[0]), "+f"(c[1]), "+f"(c[2]), "+f"(c[3])
        : "r"(a0), "r"(a1), "r"(a2), "r"(a3), "r"(b0), "r"(b1));
}

// ---------------- fast activations (saturation-safe) -------------------------
__device__ __forceinline__ float fsig(float x) {
    float e = __expf(-x);                       // -inf->inf safe
    return __fdividef(1.f, 1.f + e);
}
__device__ __forceinline__ float ftanh(float x) {
    float e = __expf(2.f * x);                  // +inf -> 1, 0 -> -1
    return 1.f - __fdividef(2.f, e + 1.f);
}

// ---------------- fence-free grid barrier ------------------------------------
// Writers publish via st.cg (L2); arrive is a release-red; poll is acquire-ld.
// Readers use __ldcg for all cross-CTA data => no stale L1, no CCTL.IVALL.
__device__ __forceinline__ void grid_barrier(unsigned& target) {
    __syncthreads();
    if (threadIdx.x == 0) {
        target += gridDim.x;
        unsigned* bar = &g_bar;
        asm volatile("red.release.gpu.global.add.u32 [%0], 1;" :: "l"(bar) : "memory");
        unsigned v;
        do {
            asm volatile("ld.acquire.gpu.global.u32 %0, [%1];" : "=r"(v) : "l"(bar) : "memory");
        } while (v < target);
    }
    __syncthreads();
}

// ---------------- persistent recurrence kernel -------------------------------
// 128 CTAs x 256 threads = 2 batch-groups (64 rows) x 64 j-groups (8 cols).
// Whh slice (both layers) pre-split to bf16 hi/lo pairs, resident in smem.
// smem layout (dynamic, bytes):
//   Bsm  uint2[2*32][258]   0      .. 132096   (kp pairs, {hi,lo})
//   Asm  uint2[128][66]     132096 .. 199680   (half-K staging)
//   Cs   float[64][36]      199680 .. 208896
//   csm  float[64][8]       208896 .. 210944
//   red  float[8]           210944 .. 210976
#define SMEM_REC 210976
__global__ void __launch_bounds__(256, 1)
k_recurrence(const float* __restrict__ Whh,
             const float* __restrict__ lng, const float* __restrict__ lnb) {
    extern __shared__ __align__(16) char sbuf[];
    uint2* Bsm          = (uint2*)sbuf;                      // [(l*32+row)*258 + kp]
    uint2 (*Asm)[66]    = (uint2(*)[66])(sbuf + 132096);     // [kp][row]
    float (*Cs)[36]     = (float(*)[36])(sbuf + 199680);
    float (*csm)[8]     = (float(*)[8])(sbuf + 208896);
    float* red          = (float*)(sbuf + 210944);

    const int tid  = threadIdx.x;
    const int lane = tid & 31;
    const int warp = tid >> 5;
    const int gid  = lane >> 2, t4 = lane & 3;
    const int cta  = blockIdx.x;             // 0..127
    const int jcta = cta & 63;               // j-group: cols [jcta*8, jcta*8+8)
    const int bm0  = (cta >> 6) * 64;        // batch-group base row
    const int wm   = warp >> 1, wn = warp & 1;  // 4x2 warps, warp tile 16x16
    unsigned target = 0;

    // ---- one-time: load + bf16-split this CTA's Whh slice (both layers) ----
    for (int idx = tid; idx < 2 * 32 * 256; idx += 256) {
        int l  = idx >> 13;
        int rm = idx & 8191;
        int rl = rm >> 8;                    // local row 0..31
        int kp = rm & 255;                   // k-pair 0..255
        int p  = jcta * 32 + rl;
        int orig = ((p & 3) << 9) | (p >> 2);
        float2 v = *(const float2*)(Whh + ((size_t)l * G4 + orig) * Dd + kp * 2);
        unsigned h = bpack(v.x, v.y);
        unsigned lo = bpack(v.x - blo(h), v.y - bhi(h));
        Bsm[(l * 32 + rl) * 258 + kp] = make_uint2(h, lo);
    }
    for (int i = tid; i < 64 * 8; i += 256) csm[i >> 3][i & 7] = 0.f;
    float lg0 = lng[tid], lg1 = lng[tid + 256];
    float lb0 = lnb[tid], lb1 = lnb[tid + 256];
    // cell-phase index precompute
    const int cb0 = bm0 + ((tid * 2) >> 3);          // it=0 row
    const int cb1 = bm0 + (((tid + 256) * 2) >> 3);  // unused form; compute below
    (void)cb1;
    __syncthreads();

    for (int t = 0; t < Tt; t++) {
#pragma unroll 1
        for (int l = 0; l < 2; l++) {
            const float* A    = (l == 0) ? g_h : g_hm;
            const float* gx   = g_Gx + ((size_t)l * Tt + t) * Bn * G4;
            float*       hout = (l == 0) ? g_hm : g_hr;
            const int    l32  = l * 32;

            // ---- prefetch gx gate values for the cell epilogue (8 LDG) ----
            float gpre[2][4];
#pragma unroll
            for (int it = 0; it < 2; it++) {
                int x    = tid + it * 256;
                int brow = x >> 3, jj = x & 7;
                int b    = bm0 + brow;
                int j    = jcta * 8 + jj;
                gpre[it][0] = __ldg(&gx[b * G4 + j]);
                gpre[it][1] = __ldg(&gx[b * G4 + 512 + j]);
                gpre[it][2] = __ldg(&gx[b * G4 + 1024 + j]);
                gpre[it][3] = __ldg(&gx[b * G4 + 1536 + j]);
            }

            float accA[2][4], accB[2][4];
#pragma unroll
            for (int n = 0; n < 2; n++)
#pragma unroll
                for (int q = 0; q < 4; q++) { accA[n][q] = 0.f; accB[n][q] = 0.f; }

#pragma unroll 1
            for (int half = 0; half < 2; half++) {
                // ---- stage A half: 64 rows x 256 k -> bf16 hi/lo pairs ----
                const float* Ag = A + (size_t)bm0 * Dd + half * 256;
#pragma unroll
                for (int r = 0; r < 16; r++) {
                    int idx = tid + r * 256;
                    int row = idx >> 6, c4 = idx & 63;
                    float4 v = __ldcg((const float4*)(Ag + (size_t)row * Dd + c4 * 4));
                    unsigned h01 = bpack(v.x, v.y);
                    unsigned h23 = bpack(v.z, v.w);
                    unsigned l01 = bpack(v.x - blo(h01), v.y - bhi(h01));
                    unsigned l23 = bpack(v.z - blo(h23), v.w - bhi(h23));
                    Asm[c4 * 2    ][row] = make_uint2(h01, l01);
                    Asm[c4 * 2 + 1][row] = make_uint2(h23, l23);
                }
                __syncthreads();

                const int mm = wm * 16 + gid;
                const int kpb = half * 128;
#pragma unroll
                for (int i = 0; i < 16; i++) {
                    uint2 a0 = Asm[i * 8 + t4    ][mm];
                    uint2 a1 = Asm[i * 8 + t4    ][mm + 8];
                    uint2 a2 = Asm[i * 8 + t4 + 4][mm];
                    uint2 a3 = Asm[i * 8 + t4 + 4][mm + 8];
#pragma unroll
                    for (int nf = 0; nf < 2; nf++) {
                        int nn = wn * 16 + nf * 8 + gid;
                        uint2 b0 = Bsm[(l32 + nn) * 258 + kpb + i * 8 + t4    ];
                        uint2 b1 = Bsm[(l32 + nn) * 258 + kpb + i * 8 + t4 + 4];
                        mma_bf16(accA[nf], a0.x, a1.x, a2.x, a3.x, b0.x, b1.x);  // hi.hi
                        mma_bf16(accB[nf], a0.y, a1.y, a2.y, a3.y, b0.x, b1.x);  // lo.hi
                        mma_bf16(accB[nf], a0.x, a1.x, a2.x, a3.x, b0.y, b1.y);  // hi.lo
                    }
                }
                __syncthreads();
            }
            // accumulators -> Cs
#pragma unroll
            for (int nf = 0; nf < 2; nf++) {
                int r0 = wm * 16 + gid;
                int c0 = wn * 16 + nf * 8 + 2 * t4;
                Cs[r0    ][c0    ] = accA[nf][0] + accB[nf][0];
                Cs[r0    ][c0 + 1] = accA[nf][1] + accB[nf][1];
                Cs[r0 + 8][c0    ] = accA[nf][2] + accB[nf][2];
                Cs[r0 + 8][c0 + 1] = accA[nf][3] + accB[nf][3];
            }
            __syncthreads();
            // LSTM cell: 64x8 = 512 elements, 2 per thread (gx preloaded)
#pragma unroll
            for (int it = 0; it < 2; it++) {
                int x    = tid + it * 256;
                int brow = x >> 3, jj = x & 7;
                int b    = bm0 + brow;
                int j    = jcta * 8 + jj;
                float gi = Cs[brow][jj * 4 + 0] + gpre[it][0];
                float gf = Cs[brow][jj * 4 + 1] + gpre[it][1];
                float gg = Cs[brow][jj * 4 + 2] + gpre[it][2];
                float go = Cs[brow][jj * 4 + 3] + gpre[it][3];
                float ii = fsig(gi);
                float ff = fsig(gf);
                float gt = ftanh(gg);
                float oo = fsig(go);
                float cn = ff * csm[brow][jj] + ii * gt;
                csm[brow][jj] = cn;
                __stcg(&hout[(size_t)b * Dd + j], oo * ftanh(cn));
            }
            grid_barrier(target);
        }
        // ---- LayerNorm: CTA handles batch row b = cta (256 threads, 2 elems) --
        {
            const float* xr = g_hr + (size_t)cta * Dd;
            float v0 = __ldcg(&xr[tid]), v1 = __ldcg(&xr[tid + 256]);
            float s = v0 + v1;
#pragma unroll
            for (int o = 16; o > 0; o >>= 1) s += __shfl_xor_sync(0xffffffffu, s, o);
            if (lane == 0) red[warp] = s;
            __syncthreads();
            float mu = (red[0] + red[1] + red[2] + red[3] +
                        red[4] + red[5] + red[6] + red[7]) * (1.f / 512.f);
            __syncthreads();
            float d0 = v0 - mu, d1 = v1 - mu;
            float vv = d0 * d0 + d1 * d1;
#pragma unroll
            for (int o = 16; o > 0; o >>= 1) vv += __shfl_xor_sync(0xffffffffu, vv, o);
            if (lane == 0) red[warp] = vv;
            __syncthreads();
            float var  = (red[0] + red[1] + red[2] + red[3] +
                          red[4] + red[5] + red[6] + red[7]) * (1.f / 512.f);
            float rstd = rsqrtf(var + 1e-5f);
            float y0 = d0 * rstd * lg0 + lb0;
            float y1 = d1 * rstd * lg1 + lb1;
            __stcg(&g_h[(size_t)cta * Dd + tid],       y0);
            __stcg(&g_h[(size_t)cta * Dd + tid + 256], y1);
            if (t > 0) {
                g_H[((size_t)(t - 1) * Bn + cta) * Dd + tid]       = y0;
                g_H[((size_t)(t - 1) * Bn + cta) * Dd + tid + 256] = y1;
            }
            __syncthreads();
        }
        grid_barrier(target);
    }
}

// ---------------- Gx GEMM, bf16x3:  C = A(MxK) * B(NxK)^T + b1 + b2 ----------
// BM=128, BN=64, 256 threads, warp tile 32x32, k-tile 16 (8 bf16 pairs).
__global__ void __launch_bounds__(256)
gemm_gx_bf16(const float* __restrict__ A, int M, int lda,
             const float* __restrict__ Bm, int N, int ldb, int K,
             const float* __restrict__ bias1, const float* __restrict__ bias2,
             float* __restrict__ C, int ldc)
{
    __shared__ uint2 Ash[8][132];
    __shared__ uint2 Bsh[8][68];

    const int tid  = threadIdx.x;
    const int lane = tid & 31;
    const int warp = tid >> 5;
    const int wn = warp & 1, wm = warp >> 1;   // 4x2 warps
    const int gid = lane >> 2, t4 = lane & 3;
    const int m0 = blockIdx.x * 128;
    const int n0 = blockIdx.y * 64;

    float acc[2][4][4];
#pragma unroll
    for (int i = 0; i < 2; i++)
#pragma unroll
        for (int j = 0; j < 4; j++)
#pragma unroll
            for (int q = 0; q < 4; q++) acc[i][j][q] = 0.f;

    // loads: A 128x16 = 512 float4 (2/thread), B 64x16 = 256 float4 (1/thread)
    float4 ra[2], rb;
    const int arow = tid >> 2,  acb = tid & 3;        // rows 0..63 (x2)
    const int brow = (tid & 255) >> 2;                // 0..63
#define LOAD_T(K0)                                                           \
    {                                                                        \
        ra[0] = *(const float4*)(A + (size_t)(m0 + arow) * lda + (K0) + acb * 4);       \
        ra[1] = *(const float4*)(A + (size_t)(m0 + arow + 64) * lda + (K0) + acb * 4);  \
        rb    = *(const float4*)(Bm + (size_t)(n0 + brow) * ldb + (K0) + acb * 4);      \
    }

    LOAD_T(0)

    for (int k0 = 0; k0 < K; k0 += 16) {
        // pack to bf16 hi/lo pairs: float4 = 2 k-pairs at kp = acb*2, acb*2+1
#pragma unroll
        for (int i = 0; i < 2; i++) {
            unsigned h01 = bpack(ra[i].x, ra[i].y);
            unsigned h23 = bpack(ra[i].z, ra[i].w);
            unsigned l01 = bpack(ra[i].x - blo(h01), ra[i].y - bhi(h01));
            unsigned l23 = bpack(ra[i].z - blo(h23), ra[i].w - bhi(h23));
            Ash[acb * 2    ][arow + i * 64] = make_uint2(h01, l01);
            Ash[acb * 2 + 1][arow + i * 64] = make_uint2(h23, l23);
        }
        {
            unsigned h01 = bpack(rb.x, rb.y);
            unsigned h23 = bpack(rb.z, rb.w);
            unsigned l01 = bpack(rb.x - blo(h01), rb.y - bhi(h01));
            unsigned l23 = bpack(rb.z - blo(h23), rb.w - bhi(h23));
            Bsh[acb * 2    ][brow] = make_uint2(h01, l01);
            Bsh[acb * 2 + 1][brow] = make_uint2(h23, l23);
        }
        __syncthreads();

        if (k0 + 16 < K) LOAD_T(k0 + 16)

        uint2 a0[2], a1[2], a2[2], a3[2];
#pragma unroll
        for (int mf = 0; mf < 2; mf++) {
            int mm = wm * 32 + mf * 16 + gid;
            a0[mf] = Ash[t4    ][mm];
            a1[mf] = Ash[t4    ][mm + 8];
            a2[mf] = Ash[t4 + 4][mm];
            a3[mf] = Ash[t4 + 4][mm + 8];
        }
#pragma unroll
        for (int nf = 0; nf < 4; nf++) {
            int nn = wn * 32 + nf * 8 + gid;
            uint2 b0 = Bsh[t4    ][nn];
            uint2 b1 = Bsh[t4 + 4][nn];
#pragma unroll
            for (int mf = 0; mf < 2; mf++) {
                mma_bf16(acc[mf][nf], a0[mf].x, a1[mf].x, a2[mf].x, a3[mf].x, b0.x, b1.x);
                mma_bf16(acc[mf][nf], a0[mf].y, a1[mf].y, a2[mf].y, a3[mf].y, b0.x, b1.x);
                mma_bf16(acc[mf][nf], a0[mf].x, a1[mf].x, a2[mf].x, a3[mf].x, b0.y, b1.y);
            }
        }
        __syncthreads();
    }

#pragma unroll
    for (int mf = 0; mf < 2; mf++)
#pragma unroll
        for (int nf = 0; nf < 4; nf++) {
            int r0 = m0 + wm * 32 + mf * 16 + gid;
            int c0 = n0 + wn * 32 + nf * 8 + 2 * t4;
#pragma unroll
            for (int q = 0; q < 4; q++) {
                int r = r0 + ((q >= 2) ? 8 : 0);
                int c = c0 + (q & 1);
                C[(size_t)r * ldc + c] = acc[mf][nf][q] + bias1[c] + bias2[c];
            }
        }
#undef LOAD_T
}

// ---------------- FC GEMM (tf32 single): C = A(MxK)*B(NxK)^T, permuted store --
template<int BM, int BN, int WM, int WN>
__global__ void __launch_bounds__(WM * WN * 32)
gemm_fc(const float* __restrict__ A, int M, int lda,
        const float* __restrict__ Bm, int N, int ldb, int K,
        const float* __restrict__ bias1,
        float* __restrict__ C, int ldc)
{
    constexpr int THREADS = WM * WN * 32;
    constexpr int PAD = 4;
    constexpr int MF = 2, NF = 4;

    __shared__ unsigned Ash[16][BM + PAD];
    __shared__ unsigned Bsh[16][BN + PAD];

    const int tid  = threadIdx.x;
    const int lane = tid & 31;
    const int warp = tid >> 5;
    const int wn = warp % WN, wm = warp / WN;
    const int gid = lane >> 2, t4 = lane & 3;
    const int m0 = blockIdx.x * BM;
    const int n0 = blockIdx.y * BN;

    float acc[MF][NF][4];
#pragma unroll
    for (int i = 0; i < MF; i++)
#pragma unroll
        for (int j = 0; j < NF; j++)
#pragma unroll
            for (int q = 0; q < 4; q++) acc[i][j][q] = 0.f;

    constexpr int LA = (BM * 16) / (THREADS * 4);
    constexpr int LB = (BN * 16) / (THREADS * 4);

    float4 ra[LA], rb[LB];

#define LOAD_T(K0)                                                          \
    {                                                                       \
        _Pragma("unroll")                                                   \
        for (int i = 0; i < LA; i++) {                                      \
            int f4 = tid + i * THREADS;                                     \
            int row = f4 >> 2, cb = f4 & 3;                                 \
            int gm = m0 + row;                                              \
            ra[i] = make_float4(0.f, 0.f, 0.f, 0.f);                        \
            if (gm < M) ra[i] = *(const float4*)(A + (size_t)gm * lda + (K0) + cb * 4); \
        }                                                                   \
        _Pragma("unroll")                                                   \
        for (int i = 0; i < LB; i++) {                                      \
            int f4 = tid + i * THREADS;                                     \
            int row = f4 >> 2, cb = f4 & 3;                                 \
            int grow = n0 + row;                                            \
            rb[i] = make_float4(0.f, 0.f, 0.f, 0.f);                        \
            if (grow < N) rb[i] = *(const float4*)(Bm + (size_t)grow * ldb + (K0) + cb * 4); \
        }                                                                   \
    }

    LOAD_T(0)

    for (int k0 = 0; k0 < K; k0 += 16) {
#pragma unroll
        for (int i = 0; i < LA; i++) {
            int f4 = tid + i * THREADS;
            int row = f4 >> 2, cb = f4 & 3;
            Ash[cb * 4 + 0][row] = f2t(ra[i].x);
            Ash[cb * 4 + 1][row] = f2t(ra[i].y);
            Ash[cb * 4 + 2][row] = f2t(ra[i].z);
            Ash[cb * 4 + 3][row] = f2t(ra[i].w);
        }
#pragma unroll
        for (int i = 0; i < LB; i++) {
            int f4 = tid + i * THREADS;
            int row = f4 >> 2, cb = f4 & 3;
            Bsh[cb * 4 + 0][row] = f2t(rb[i].x);
            Bsh[cb * 4 + 1][row] = f2t(rb[i].y);
            Bsh[cb * 4 + 2][row] = f2t(rb[i].z);
            Bsh[cb * 4 + 3][row] = f2t(rb[i].w);
        }
        __syncthreads();

        if (k0 + 16 < K) LOAD_T(k0 + 16)

#pragma unroll
        for (int ks = 0; ks < 2; ks++) {
            const int kb = ks * 8;
            unsigned ah[MF][4], bh[NF][2];
#pragma unroll
            for (int mf = 0; mf < MF; mf++) {
                int mm = wm * 32 + mf * 16 + gid;
                ah[mf][0] = Ash[kb + t4    ][mm];
                ah[mf][1] = Ash[kb + t4    ][mm + 8];
                ah[mf][2] = Ash[kb + t4 + 4][mm];
                ah[mf][3] = Ash[kb + t4 + 4][mm + 8];
            }
#pragma unroll
            for (int nf = 0; nf < NF; nf++) {
                int nn = wn * 32 + nf * 8 + gid;
                bh[nf][0] = Bsh[kb + t4    ][nn];
                bh[nf][1] = Bsh[kb + t4 + 4][nn];
            }
#pragma unroll
            for (int mf = 0; mf < MF; mf++)
#pragma unroll
                for (int nf = 0; nf < NF; nf++)
                    mma_tf32(acc[mf][nf], ah[mf], bh[nf]);
        }
        __syncthreads();
    }

#pragma unroll
    for (int mf = 0; mf < MF; mf++)
#pragma unroll
        for (int nf = 0; nf < NF; nf++) {
            int r0 = m0 + wm * 32 + mf * 16 + gid;
            int c0 = n0 + wn * 32 + nf * 8 + 2 * t4;
#pragma unroll
            for (int q = 0; q < 4; q++) {
                int r = r0 + ((q >= 2) ? 8 : 0);
                int c = c0 + (q & 1);
                if (r < M && c < N) {
                    int orow = (r & 127) * Ll + (r >> 7);
                    C[(size_t)orow * ldc + c] = acc[mf][nf][q] + bias1[c];
                }
            }
        }
#undef LOAD_T
}

// ---------------- in-place log_softmax, rows of 10000 ------------------------
__global__ void k_lsm(float* __restrict__ out) {
    __shared__ float row[Vv];
    __shared__ float red[8];
    float* p = out + (size_t)blockIdx.x * Vv;
    int tid = threadIdx.x;            // 256 threads

    float mx = -1e30f;
    float4*       r4 = (float4*)row;
    const float4* p4 = (const float4*)p;
    for (int i = tid; i < Vv / 4; i += 256) {
        float4 v = p4[i];
        r4[i] = v;
        mx = fmaxf(mx, fmaxf(fmaxf(v.x, v.y), fmaxf(v.z, v.w)));
    }
#pragma unroll
    for (int o = 16; o > 0; o >>= 1) mx = fmaxf(mx, __shfl_xor_sync(0xffffffffu, mx, o));
    if ((tid & 31) == 0) red[tid >> 5] = mx;
    __syncthreads();
    mx = red[0];
#pragma unroll
    for (int i = 1; i < 8; i++) mx = fmaxf(mx, red[i]);

    float s = 0.f;
    for (int i = tid; i < Vv; i += 256) s += expf(row[i] - mx);
#pragma unroll
    for (int o = 16; o > 0; o >>= 1) s += __shfl_xor_sync(0xffffffffu, s, o);
    __syncthreads();
    if ((tid & 31) == 0) red[tid >> 5] = s;
    __syncthreads();
    s = red[0] + red[1] + red[2] + red[3] + red[4] + red[5] + red[6] + red[7];
    float lse = mx + logf(s);

    for (int i = tid; i < Vv; i += 256) p[i] = row[i] - lse;
}

// ---------------- host launcher ----------------------------------------------
extern "C" void kernel_launch(void* const* d_in, const int* in_sizes, int n_in,
                              void* d_out, int out_size) {
    const float* features = (const float*)d_in[0];
    const void*  caption  = d_in[1];
    const float* embW     = (const float*)d_in[2];
    const float* Wih      = (const float*)d_in[3];
    const float* Whh      = (const float*)d_in[4];
    const float* bih      = (const float*)d_in[5];
    const float* bhh      = (const float*)d_in[6];
    const float* lng      = (const float*)d_in[7];
    const float* lnb      = (const float*)d_in[8];
    const float* fcW      = (const float*)d_in[9];
    const float* fcb      = (const float*)d_in[10];
    float*       out      = (float*)d_out;

    float *pX, *pGx, *pH;
    cudaGetSymbolAddress((void**)&pX,  g_X);
    cudaGetSymbolAddress((void**)&pGx, g_Gx);
    cudaGetSymbolAddress((void**)&pH,  g_H);

    cudaFuncSetAttribute(k_recurrence,
                         cudaFuncAttributeMaxDynamicSharedMemorySize, SMEM_REC);

    k_init<<<256, 256>>>();
    k_detect<<<1, 256>>>((const int*)caption);
    k_build_x<<<Tt * Bn, 128>>>(features, caption, embW);

    // Gx = X @ Wih^T + bih + bhh   (both layers, bf16x3)
    for (int l = 0; l < 2; l++)
        gemm_gx_bf16<<<dim3(33, 32), 256>>>(
            pX, Tt * Bn, Dd,
            Wih + (size_t)l * G4 * Dd, G4, Dd, Dd,
            bih + l * G4, bhh + l * G4,
            pGx + (size_t)l * Tt * Bn * G4, G4);

    // full 33-step recurrence in ONE persistent kernel (single wave)
    k_recurrence<<<128, 256, SMEM_REC>>>(Whh, lng, lnb);

    // FC: logits = H @ fcW^T + fcb  (single tf32, permuted store)
    gemm_fc<128, 64, 4, 2><<<dim3(32, 157), 256>>>(
        pH, Ll * Bn, Dd, fcW, Vv, Dd, Dd,
        fcb, out, Vv);

    k_lsm<<<Ll * Bn, 256>>>(out);
}